// round 5
// baseline (speedup 1.0000x reference)
#include <cuda_runtime.h>
#include <cuda_bf16.h>
#include <math.h>

// Problem constants (fixed by the dataset)
#define NN 50000
#define EE 800000
#define KK 256     // feature / hidden width (K dim of every GEMM)
#define CC 40      // n_classes

// ---------------- scratch (static device globals; no allocation) -------------
__device__ float g_Y[(size_t)NN * KK];      // GEMM output buffer
__device__ float g_h[(size_t)NN * KK];      // post-aggregation activations
__device__ int   g_counts[NN];
__device__ int   g_indptr[NN + 1];
__device__ int   g_cursor[NN];
__device__ int   g_srcsorted[EE];
__device__ int   g_blocksums[64];

// ---------------- CSR build --------------------------------------------------
__global__ void k_zero_counts(int n) {
    int i = blockIdx.x * blockDim.x + threadIdx.x;
    if (i < n) g_counts[i] = 0;
}

// NOTE: edge_index is int32 (JAX default x64-disabled: .astype(jnp.int64) -> int32).
__global__ void k_hist(const int* __restrict__ edge, int E, int n) {
    int e = blockIdx.x * blockDim.x + threadIdx.x;
    if (e < E) {
        unsigned d = (unsigned)edge[E + e];
        if (d < (unsigned)n) atomicAdd(&g_counts[d], 1);
    }
}

// pass 1: per-block inclusive scan of counts -> g_indptr, block totals -> g_blocksums
__global__ void k_scan1(int n) {
    __shared__ int sh[1024];
    int i = blockIdx.x * 1024 + threadIdx.x;
    int v = (i < n) ? g_counts[i] : 0;
    sh[threadIdx.x] = v;
    __syncthreads();
    for (int off = 1; off < 1024; off <<= 1) {
        int t = (threadIdx.x >= off) ? sh[threadIdx.x - off] : 0;
        __syncthreads();
        sh[threadIdx.x] += t;
        __syncthreads();
    }
    if (i < n) g_indptr[i] = sh[threadIdx.x];          // inclusive within block
    if (threadIdx.x == 1023) g_blocksums[blockIdx.x] = sh[1023];
}

// pass 2: exclusive scan of block sums (<=64 blocks)
__global__ void k_scan2(int nb) {
    __shared__ int sh[64];
    int t = threadIdx.x;
    int v = (t < nb) ? g_blocksums[t] : 0;
    sh[t] = v;
    __syncthreads();
    for (int off = 1; off < 64; off <<= 1) {
        int x = (t >= off) ? sh[t - off] : 0;
        __syncthreads();
        sh[t] += x;
        __syncthreads();
    }
    g_blocksums[t] = sh[t] - v;   // exclusive
}

// pass 3: make exclusive global indptr, init cursor
__global__ void k_scan3(int n, int Etot) {
    int i = blockIdx.x * 1024 + threadIdx.x;
    if (i < n) {
        int excl = g_indptr[i] - g_counts[i] + g_blocksums[blockIdx.x];
        g_indptr[i] = excl;
        g_cursor[i] = excl;
    }
    if (i == 0) g_indptr[n] = Etot;
}

__global__ void k_scatter(const int* __restrict__ edge, int E, int n) {
    int e = blockIdx.x * blockDim.x + threadIdx.x;
    if (e < E) {
        unsigned d = (unsigned)edge[E + e];
        unsigned s = (unsigned)edge[e];
        if (d < (unsigned)n && s < (unsigned)n) {
            int pos = atomicAdd(&g_cursor[d], 1);
            g_srcsorted[pos] = (int)s;
        }
    }
}

// ---------------- fp32 tiled GEMM: g_Y[M,Ncols] = A[M,256] @ B[256,Ncols] ----
// A is either the external pointer (useH == 0) or the device-global g_h.
__global__ void k_gemm(const float* __restrict__ A_ext, const float* __restrict__ B,
                       int M, int Ncols, int useH) {
    const float* __restrict__ A = useH ? g_h : A_ext;
    float* __restrict__ C = g_Y;
    __shared__ __align__(16) float As[16][64];
    __shared__ __align__(16) float Bs[16][64];
    const int K = KK;
    int tid = threadIdx.x;
    int bm = blockIdx.x * 64, bn = blockIdx.y * 64;
    int arow = tid >> 2, acol = (tid & 3) * 4;
    int brow = tid >> 4, bcol = (tid & 15) * 4;
    int ty = tid >> 4, tx = tid & 15;
    float acc[4][4] = {};
    for (int k0 = 0; k0 < K; k0 += 16) {
        float4 av = make_float4(0.f, 0.f, 0.f, 0.f);
        int ar = bm + arow;
        if (ar < M) av = *(const float4*)&A[(size_t)ar * K + k0 + acol];
        As[acol + 0][arow] = av.x;
        As[acol + 1][arow] = av.y;
        As[acol + 2][arow] = av.z;
        As[acol + 3][arow] = av.w;

        float4 bv = make_float4(0.f, 0.f, 0.f, 0.f);
        int bc = bn + bcol;
        if (bc + 3 < Ncols) {
            bv = *(const float4*)&B[(size_t)(k0 + brow) * Ncols + bc];
        } else {
            float t0 = (bc + 0 < Ncols) ? B[(size_t)(k0 + brow) * Ncols + bc + 0] : 0.f;
            float t1 = (bc + 1 < Ncols) ? B[(size_t)(k0 + brow) * Ncols + bc + 1] : 0.f;
            float t2 = (bc + 2 < Ncols) ? B[(size_t)(k0 + brow) * Ncols + bc + 2] : 0.f;
            float t3 = (bc + 3 < Ncols) ? B[(size_t)(k0 + brow) * Ncols + bc + 3] : 0.f;
            bv = make_float4(t0, t1, t2, t3);
        }
        *(float4*)&Bs[brow][bcol] = bv;
        __syncthreads();
#pragma unroll
        for (int kk = 0; kk < 16; kk++) {
            float4 a4 = *(const float4*)&As[kk][ty * 4];
            float4 b4 = *(const float4*)&Bs[kk][tx * 4];
            float a[4] = {a4.x, a4.y, a4.z, a4.w};
            float b[4] = {b4.x, b4.y, b4.z, b4.w};
#pragma unroll
            for (int i = 0; i < 4; i++)
#pragma unroll
                for (int j = 0; j < 4; j++) acc[i][j] += a[i] * b[j];
        }
        __syncthreads();
    }
#pragma unroll
    for (int i = 0; i < 4; i++) {
        int r = bm + ty * 4 + i;
        if (r >= M) continue;
#pragma unroll
        for (int j = 0; j < 4; j++) {
            int c = bn + tx * 4 + j;
            if (c < Ncols) C[(size_t)r * Ncols + c] = acc[i][j];
        }
    }
}

// ---------------- aggregation (256-wide) + bias + relu: g_h = relu(agg(g_Y)+b)
__global__ void k_agg_relu(const float* __restrict__ bias) {
    const float* __restrict__ Y = g_Y;
    __shared__ int sidx[64];
    int node = blockIdx.x;
    int start = g_indptr[node], end = g_indptr[node + 1];
    float acc = 0.f;
    for (int base = start; base < end; base += 64) {
        int m = end - base;
        if (m > 64) m = 64;
        if (threadIdx.x < m) sidx[threadIdx.x] = g_srcsorted[base + threadIdx.x];
        __syncthreads();
#pragma unroll 4
        for (int i = 0; i < m; i++) {
            acc += Y[(size_t)sidx[i] * KK + threadIdx.x];
        }
        __syncthreads();
    }
    g_h[(size_t)node * KK + threadIdx.x] = fmaxf(acc + bias[threadIdx.x], 0.f);
}

// ---------------- aggregation (40-wide) + bias + log_softmax -----------------
__global__ void k_agg_lsm(const float* __restrict__ b3, float* __restrict__ out, int n) {
    const float* __restrict__ Y3 = g_Y;
    int warp = (blockIdx.x * blockDim.x + threadIdx.x) >> 5;
    int lane = threadIdx.x & 31;
    if (warp >= n) return;
    int start = g_indptr[warp], end = g_indptr[warp + 1];
    float acc0 = 0.f, acc1 = 0.f;
    for (int e = start; e < end; e++) {
        int s = g_srcsorted[e];
        acc0 += Y3[(size_t)s * CC + lane];
        if (lane < 8) acc1 += Y3[(size_t)s * CC + 32 + lane];
    }
    float v0 = acc0 + b3[lane];
    float v1 = (lane < 8) ? (acc1 + b3[32 + lane]) : -1e30f;
    float m = fmaxf(v0, v1);
#pragma unroll
    for (int off = 16; off; off >>= 1) m = fmaxf(m, __shfl_xor_sync(0xffffffffu, m, off));
    float s0 = expf(v0 - m) + ((lane < 8) ? expf(v1 - m) : 0.f);
#pragma unroll
    for (int off = 16; off; off >>= 1) s0 += __shfl_xor_sync(0xffffffffu, s0, off);
    float lse = m + logf(s0);
    out[(size_t)warp * CC + lane] = v0 - lse;
    if (lane < 8) out[(size_t)warp * CC + 32 + lane] = v1 - lse;
}

// ---------------- tail: node_count scalar(s) ---------------------------------
__global__ void k_tail(float* __restrict__ out, int begin, int total, float val) {
    int i = begin + blockIdx.x * blockDim.x + threadIdx.x;
    if (i < total) out[i] = val;
}

// ---------------- launch -----------------------------------------------------
extern "C" void kernel_launch(void* const* d_in, const int* in_sizes, int n_in,
                              void* d_out, int out_size) {
    const float* features = (const float*)d_in[0];
    const int*   edge     = (const int*)d_in[1];   // int32! (JAX x64 disabled)
    // d_in[2]=labels, d_in[3]=mask : unused
    const float* W1 = (const float*)d_in[4];
    const float* b1 = (const float*)d_in[5];
    const float* W2 = (const float*)d_in[6];
    const float* b2 = (const float*)d_in[7];
    const float* W3 = (const float*)d_in[8];
    const float* b3 = (const float*)d_in[9];
    float* out = (float*)d_out;

    int n = in_sizes[0] / KK;      // 50000
    int E = in_sizes[1] / 2;       // 800000 (edge_index has 2*E int32 elements)

    // ---- CSR by dst ----
    k_zero_counts<<<(n + 255) / 256, 256>>>(n);
    k_hist<<<(E + 255) / 256, 256>>>(edge, E, n);
    int NB = (n + 1023) / 1024;
    k_scan1<<<NB, 1024>>>(n);
    k_scan2<<<1, 64>>>(NB);
    k_scan3<<<NB, 1024>>>(n, E);
    k_scatter<<<(E + 255) / 256, 256>>>(edge, E, n);

    // ---- layer 1: Y = X @ W1 ; h = relu(agg(Y) + b1) ----
    dim3 g256((n + 63) / 64, (KK + 63) / 64);
    k_gemm<<<g256, 256>>>(features, W1, n, KK, 0);
    k_agg_relu<<<n, 256>>>(b1);

    // ---- layer 2: Y = h @ W2 ; h = relu(agg(Y) + b2) ----
    k_gemm<<<g256, 256>>>(nullptr, W2, n, KK, 1);
    k_agg_relu<<<n, 256>>>(b2);

    // ---- layer 3: Y3 = h @ W3 (N x 40) ; out = log_softmax(agg(Y3) + b3) ----
    dim3 g40((n + 63) / 64, (CC + 63) / 64);
    k_gemm<<<g40, 256>>>(nullptr, W3, n, CC, 1);
    k_agg_lsm<<<(n * 32 + 255) / 256, 256>>>(b3, out, n);

    // ---- node_count tail (output = [ret (N*C floats), node_count]) ----
    int nc_begin = n * CC;
    if (out_size > nc_begin) {
        int rem = out_size - nc_begin;
        k_tail<<<(rem + 255) / 256, 256>>>(out, nc_begin, out_size, 150000.0f);
    }
}

// round 9
// speedup vs baseline: 1.3790x; 1.3790x over previous
#include <cuda_runtime.h>
#include <cuda_bf16.h>
#include <math.h>

typedef unsigned int u32;

// Problem constants (fixed by the dataset)
#define NN 50000
#define EE 800000
#define KK 256     // feature / hidden width
#define CC 40      // n_classes

// ---------------- scratch (static device globals; no allocation) -------------
__device__ float g_Y[(size_t)NN * KK];      // GEMM output buffer
__device__ float g_h[(size_t)NN * KK];      // post-aggregation activations
__device__ int   g_counts[NN];
__device__ int   g_indptr[NN + 1];
__device__ int   g_cursor[NN];
__device__ int   g_srcsorted[EE];
__device__ int   g_blocksums[64];

// bf16 hi/lo transposed weights: Wt[n][k] = W[k][n]  (256x256 each)
__device__ __nv_bfloat16 g_W1hi[65536];
__device__ __nv_bfloat16 g_W1lo[65536];
__device__ __nv_bfloat16 g_W2hi[65536];
__device__ __nv_bfloat16 g_W2lo[65536];

// ---------------- weight prep: W[k][n] -> Wt hi/lo [n][k] --------------------
__global__ void k_prepW(const float* __restrict__ W1, const float* __restrict__ W2) {
    int idx = blockIdx.x * blockDim.x + threadIdx.x;   // 65536
    if (idx >= 65536) return;
    int k = idx & 255, n = idx >> 8;
    float w1 = W1[k * 256 + n];
    __nv_bfloat16 h1 = __float2bfloat16_rn(w1);
    g_W1hi[n * 256 + k] = h1;
    g_W1lo[n * 256 + k] = __float2bfloat16_rn(w1 - __bfloat162float(h1));
    float w2 = W2[k * 256 + n];
    __nv_bfloat16 h2 = __float2bfloat16_rn(w2);
    g_W2hi[n * 256 + k] = h2;
    g_W2lo[n * 256 + k] = __float2bfloat16_rn(w2 - __bfloat162float(h2));
}

// ---------------- HMMA bf16 hi/lo GEMM: g_Y[M,256] = A[M,256] @ W ------------
// block 128x128, 8 warps of 32x64, K-chunk 32, SMEM stride 40 (conflict-free)
#define SSTR 40

__device__ __forceinline__ void mma_bf16(float* c, const u32* a, u32 b0, u32 b1) {
    asm volatile(
        "mma.sync.aligned.m16n8k16.row.col.f32.bf16.bf16.f32 "
        "{%0,%1,%2,%3}, {%4,%5,%6,%7}, {%8,%9}, {%0,%1,%2,%3};\n"
        : "+f"(c[0]), "+f"(c[1]), "+f"(c[2]), "+f"(c[3])
        : "r"(a[0]), "r"(a[1]), "r"(a[2]), "r"(a[3]), "r"(b0), "r"(b1));
}

__global__ void __launch_bounds__(256, 2) k_gemm_mma(const float* __restrict__ A_ext,
                                                     int M, int which) {
    const float* __restrict__ A = which ? g_h : A_ext;
    const __nv_bfloat16* __restrict__ Whi = which ? g_W2hi : g_W1hi;
    const __nv_bfloat16* __restrict__ Wlo = which ? g_W2lo : g_W1lo;

    __shared__ __nv_bfloat16 sA[2][128][SSTR];   // [hi/lo][m][k]
    __shared__ __nv_bfloat16 sB[2][128][SSTR];   // [hi/lo][n][k]

    int tid = threadIdx.x;
    int wid = tid >> 5, lane = tid & 31;
    int g = lane >> 2, tg = lane & 3;
    int wm = (wid & 3) * 32, wn = (wid >> 2) * 64;
    int bm = blockIdx.x * 128, bn = blockIdx.y * 128;

    float acc[2][8][4];
#pragma unroll
    for (int i = 0; i < 2; i++)
#pragma unroll
        for (int j = 0; j < 8; j++)
#pragma unroll
            for (int q = 0; q < 4; q++) acc[i][j][q] = 0.f;

    int lr = tid >> 1;                 // load row (0..127)
    int lc = (tid & 1) * 16;           // load col base (0 or 16)
    bool arow_ok = (bm + lr) < M;
    const float4* ap = (const float4*)(A + (size_t)(bm + lr) * KK + lc);

    for (int kc = 0; kc < KK; kc += 32) {
        // ---- A: fp32 -> bf16 hi/lo ----
#pragma unroll
        for (int j = 0; j < 4; j++) {
            float4 v = arow_ok ? ap[kc / 4 + j] : make_float4(0.f, 0.f, 0.f, 0.f);
            __nv_bfloat16 h0 = __float2bfloat16_rn(v.x), h1 = __float2bfloat16_rn(v.y);
            __nv_bfloat16 h2 = __float2bfloat16_rn(v.z), h3 = __float2bfloat16_rn(v.w);
            __nv_bfloat162 hh01(h0, h1), hh23(h2, h3);
            __nv_bfloat162 ll01(__float2bfloat16_rn(v.x - __bfloat162float(h0)),
                                __float2bfloat16_rn(v.y - __bfloat162float(h1)));
            __nv_bfloat162 ll23(__float2bfloat16_rn(v.z - __bfloat162float(h2)),
                                __float2bfloat16_rn(v.w - __bfloat162float(h3)));
            *(u32*)&sA[0][lr][lc + 4 * j]     = *(u32*)&hh01;
            *(u32*)&sA[0][lr][lc + 4 * j + 2] = *(u32*)&hh23;
            *(u32*)&sA[1][lr][lc + 4 * j]     = *(u32*)&ll01;
            *(u32*)&sA[1][lr][lc + 4 * j + 2] = *(u32*)&ll23;
        }
        // ---- B: copy pre-split bf16 ----
        {
            const uint4* sh = (const uint4*)(Whi + (size_t)(bn + lr) * 256 + kc + lc);
            const uint4* sl = (const uint4*)(Wlo + (size_t)(bn + lr) * 256 + kc + lc);
            *(uint4*)&sB[0][lr][lc]     = sh[0];
            *(uint4*)&sB[0][lr][lc + 8] = sh[1];
            *(uint4*)&sB[1][lr][lc]     = sl[0];
            *(uint4*)&sB[1][lr][lc + 8] = sl[1];
        }
        __syncthreads();

#pragma unroll
        for (int ks = 0; ks < 2; ks++) {
            int kb = ks * 16;
            u32 ahi[2][4], alo[2][4];
#pragma unroll
            for (int mi = 0; mi < 2; mi++) {
                int r0 = wm + mi * 16 + g;
                ahi[mi][0] = *(const u32*)&sA[0][r0][kb + tg * 2];
                ahi[mi][1] = *(const u32*)&sA[0][r0 + 8][kb + tg * 2];
                ahi[mi][2] = *(const u32*)&sA[0][r0][kb + tg * 2 + 8];
                ahi[mi][3] = *(const u32*)&sA[0][r0 + 8][kb + tg * 2 + 8];
                alo[mi][0] = *(const u32*)&sA[1][r0][kb + tg * 2];
                alo[mi][1] = *(const u32*)&sA[1][r0 + 8][kb + tg * 2];
                alo[mi][2] = *(const u32*)&sA[1][r0][kb + tg * 2 + 8];
                alo[mi][3] = *(const u32*)&sA[1][r0 + 8][kb + tg * 2 + 8];
            }
#pragma unroll
            for (int ni = 0; ni < 8; ni++) {
                int nr = wn + ni * 8 + g;
                u32 bh0 = *(const u32*)&sB[0][nr][kb + tg * 2];
                u32 bh1 = *(const u32*)&sB[0][nr][kb + tg * 2 + 8];
                u32 bl0 = *(const u32*)&sB[1][nr][kb + tg * 2];
                u32 bl1 = *(const u32*)&sB[1][nr][kb + tg * 2 + 8];
#pragma unroll
                for (int mi = 0; mi < 2; mi++) {
                    mma_bf16(acc[mi][ni], ahi[mi], bh0, bh1);
                    mma_bf16(acc[mi][ni], ahi[mi], bl0, bl1);
                    mma_bf16(acc[mi][ni], alo[mi], bh0, bh1);
                }
            }
        }
        __syncthreads();
    }

    // ---- epilogue: acc -> g_Y (fp32) ----
#pragma unroll
    for (int mi = 0; mi < 2; mi++) {
        int row0 = bm + wm + mi * 16 + g;
#pragma unroll
        for (int ni = 0; ni < 8; ni++) {
            int col = bn + wn + ni * 8 + tg * 2;
            if (row0 < M)
                *(float2*)&g_Y[(size_t)row0 * KK + col] =
                    make_float2(acc[mi][ni][0], acc[mi][ni][1]);
            if (row0 + 8 < M)
                *(float2*)&g_Y[(size_t)(row0 + 8) * KK + col] =
                    make_float2(acc[mi][ni][2], acc[mi][ni][3]);
        }
    }
}

// ---------------- CSR build --------------------------------------------------
__global__ void k_zero_counts(int n) {
    int i = blockIdx.x * blockDim.x + threadIdx.x;
    if (i < n) g_counts[i] = 0;
}
__global__ void k_hist(const int* __restrict__ edge, int E, int n) {
    int e = blockIdx.x * blockDim.x + threadIdx.x;
    if (e < E) {
        unsigned d = (unsigned)edge[E + e];
        if (d < (unsigned)n) atomicAdd(&g_counts[d], 1);
    }
}
__global__ void k_scan1(int n) {
    __shared__ int sh[1024];
    int i = blockIdx.x * 1024 + threadIdx.x;
    int v = (i < n) ? g_counts[i] : 0;
    sh[threadIdx.x] = v;
    __syncthreads();
    for (int off = 1; off < 1024; off <<= 1) {
        int t = (threadIdx.x >= off) ? sh[threadIdx.x - off] : 0;
        __syncthreads();
        sh[threadIdx.x] += t;
        __syncthreads();
    }
    if (i < n) g_indptr[i] = sh[threadIdx.x];
    if (threadIdx.x == 1023) g_blocksums[blockIdx.x] = sh[1023];
}
__global__ void k_scan2(int nb) {
    __shared__ int sh[64];
    int t = threadIdx.x;
    int v = (t < nb) ? g_blocksums[t] : 0;
    sh[t] = v;
    __syncthreads();
    for (int off = 1; off < 64; off <<= 1) {
        int x = (t >= off) ? sh[t - off] : 0;
        __syncthreads();
        sh[t] += x;
        __syncthreads();
    }
    g_blocksums[t] = sh[t] - v;
}
__global__ void k_scan3(int n, int Etot) {
    int i = blockIdx.x * 1024 + threadIdx.x;
    if (i < n) {
        int excl = g_indptr[i] - g_counts[i] + g_blocksums[blockIdx.x];
        g_indptr[i] = excl;
        g_cursor[i] = excl;
    }
    if (i == 0) g_indptr[n] = Etot;
}
__global__ void k_scatter(const int* __restrict__ edge, int E, int n) {
    int e = blockIdx.x * blockDim.x + threadIdx.x;
    if (e < E) {
        unsigned d = (unsigned)edge[E + e];
        unsigned s = (unsigned)edge[e];
        if (d < (unsigned)n && s < (unsigned)n) {
            int pos = atomicAdd(&g_cursor[d], 1);
            g_srcsorted[pos] = (int)s;
        }
    }
}

// ---------------- fp32 tiled GEMM (layer 3 only, N=40) -----------------------
__global__ void k_gemm(const float* __restrict__ B, int M, int Ncols) {
    const float* __restrict__ A = g_h;
    float* __restrict__ C = g_Y;
    __shared__ __align__(16) float As[16][64];
    __shared__ __align__(16) float Bs[16][64];
    const int K = KK;
    int tid = threadIdx.x;
    int bm = blockIdx.x * 64, bn = blockIdx.y * 64;
    int arow = tid >> 2, acol = (tid & 3) * 4;
    int brow = tid >> 4, bcol = (tid & 15) * 4;
    int ty = tid >> 4, tx = tid & 15;
    float acc[4][4] = {};
    for (int k0 = 0; k0 < K; k0 += 16) {
        float4 av = make_float4(0.f, 0.f, 0.f, 0.f);
        int ar = bm + arow;
        if (ar < M) av = *(const float4*)&A[(size_t)ar * K + k0 + acol];
        As[acol + 0][arow] = av.x;
        As[acol + 1][arow] = av.y;
        As[acol + 2][arow] = av.z;
        As[acol + 3][arow] = av.w;
        float4 bv = make_float4(0.f, 0.f, 0.f, 0.f);
        int bc = bn + bcol;
        if (bc + 3 < Ncols) {
            bv = *(const float4*)&B[(size_t)(k0 + brow) * Ncols + bc];
        } else {
            float t0 = (bc + 0 < Ncols) ? B[(size_t)(k0 + brow) * Ncols + bc + 0] : 0.f;
            float t1 = (bc + 1 < Ncols) ? B[(size_t)(k0 + brow) * Ncols + bc + 1] : 0.f;
            float t2 = (bc + 2 < Ncols) ? B[(size_t)(k0 + brow) * Ncols + bc + 2] : 0.f;
            float t3 = (bc + 3 < Ncols) ? B[(size_t)(k0 + brow) * Ncols + bc + 3] : 0.f;
            bv = make_float4(t0, t1, t2, t3);
        }
        *(float4*)&Bs[brow][bcol] = bv;
        __syncthreads();
#pragma unroll
        for (int kk = 0; kk < 16; kk++) {
            float4 a4 = *(const float4*)&As[kk][ty * 4];
            float4 b4 = *(const float4*)&Bs[kk][tx * 4];
            float a[4] = {a4.x, a4.y, a4.z, a4.w};
            float b[4] = {b4.x, b4.y, b4.z, b4.w};
#pragma unroll
            for (int i = 0; i < 4; i++)
#pragma unroll
                for (int j = 0; j < 4; j++) acc[i][j] += a[i] * b[j];
        }
        __syncthreads();
    }
#pragma unroll
    for (int i = 0; i < 4; i++) {
        int r = bm + ty * 4 + i;
        if (r >= M) continue;
#pragma unroll
        for (int j = 0; j < 4; j++) {
            int c = bn + tx * 4 + j;
            if (c < Ncols) C[(size_t)r * Ncols + c] = acc[i][j];
        }
    }
}

// ---------------- aggregation (256-wide) + bias + relu -----------------------
__global__ void k_agg_relu(const float* __restrict__ bias) {
    const float* __restrict__ Y = g_Y;
    __shared__ int sidx[64];
    int node = blockIdx.x;
    int start = g_indptr[node], end = g_indptr[node + 1];
    float acc = 0.f;
    for (int base = start; base < end; base += 64) {
        int m = end - base;
        if (m > 64) m = 64;
        if (threadIdx.x < m) sidx[threadIdx.x] = g_srcsorted[base + threadIdx.x];
        __syncthreads();
#pragma unroll 4
        for (int i = 0; i < m; i++) {
            acc += Y[(size_t)sidx[i] * KK + threadIdx.x];
        }
        __syncthreads();
    }
    g_h[(size_t)node * KK + threadIdx.x] = fmaxf(acc + bias[threadIdx.x], 0.f);
}

// ---------------- aggregation (40-wide) + bias + log_softmax -----------------
__global__ void k_agg_lsm(const float* __restrict__ b3, float* __restrict__ out, int n) {
    const float* __restrict__ Y3 = g_Y;
    int warp = (blockIdx.x * blockDim.x + threadIdx.x) >> 5;
    int lane = threadIdx.x & 31;
    if (warp >= n) return;
    int start = g_indptr[warp], end = g_indptr[warp + 1];
    float acc0 = 0.f, acc1 = 0.f;
    for (int e = start; e < end; e++) {
        int s = g_srcsorted[e];
        acc0 += Y3[(size_t)s * CC + lane];
        if (lane < 8) acc1 += Y3[(size_t)s * CC + 32 + lane];
    }
    float v0 = acc0 + b3[lane];
    float v1 = (lane < 8) ? (acc1 + b3[32 + lane]) : -1e30f;
    float m = fmaxf(v0, v1);
#pragma unroll
    for (int off = 16; off; off >>= 1) m = fmaxf(m, __shfl_xor_sync(0xffffffffu, m, off));
    float s0 = expf(v0 - m) + ((lane < 8) ? expf(v1 - m) : 0.f);
#pragma unroll
    for (int off = 16; off; off >>= 1) s0 += __shfl_xor_sync(0xffffffffu, s0, off);
    float lse = m + logf(s0);
    out[(size_t)warp * CC + lane] = v0 - lse;
    if (lane < 8) out[(size_t)warp * CC + 32 + lane] = v1 - lse;
}

// ---------------- tail: node_count scalar(s) ---------------------------------
__global__ void k_tail(float* __restrict__ out, int begin, int total, float val) {
    int i = begin + blockIdx.x * blockDim.x + threadIdx.x;
    if (i < total) out[i] = val;
}

// ---------------- launch -----------------------------------------------------
extern "C" void kernel_launch(void* const* d_in, const int* in_sizes, int n_in,
                              void* d_out, int out_size) {
    const float* features = (const float*)d_in[0];
    const int*   edge     = (const int*)d_in[1];   // int32 (JAX x64 disabled)
    const float* W1 = (const float*)d_in[4];
    const float* b1 = (const float*)d_in[5];
    const float* W2 = (const float*)d_in[6];
    const float* b2 = (const float*)d_in[7];
    const float* W3 = (const float*)d_in[8];
    const float* b3 = (const float*)d_in[9];
    float* out = (float*)d_out;

    int n = in_sizes[0] / KK;      // 50000
    int E = in_sizes[1] / 2;       // 800000

    // ---- weight prep + CSR by dst ----
    k_prepW<<<256, 256>>>(W1, W2);
    k_zero_counts<<<(n + 255) / 256, 256>>>(n);
    k_hist<<<(E + 255) / 256, 256>>>(edge, E, n);
    int NB = (n + 1023) / 1024;
    k_scan1<<<NB, 1024>>>(n);
    k_scan2<<<1, 64>>>(NB);
    k_scan3<<<NB, 1024>>>(n, E);
    k_scatter<<<(E + 255) / 256, 256>>>(edge, E, n);

    dim3 gmm((n + 127) / 128, 2);

    // ---- layer 1: Y = X @ W1 (HMMA) ; h = relu(agg(Y) + b1) ----
    k_gemm_mma<<<gmm, 256>>>(features, n, 0);
    k_agg_relu<<<n, 256>>>(b1);

    // ---- layer 2: Y = h @ W2 (HMMA) ; h = relu(agg(Y) + b2) ----
    k_gemm_mma<<<gmm, 256>>>(nullptr, n, 1);
    k_agg_relu<<<n, 256>>>(b2);

    // ---- layer 3: Y3 = h @ W3 (N x 40, SIMT) ; out = log_softmax(agg+b3) ----
    dim3 g40((n + 63) / 64, (CC + 63) / 64);
    k_gemm<<<g40, 256>>>(W3, n, CC);
    k_agg_lsm<<<(n * 32 + 255) / 256, 256>>>(b3, out, n);

    // ---- node_count tail ----
    int nc_begin = n * CC;
    if (out_size > nc_begin) {
        int rem = out_size - nc_begin;
        k_tail<<<(rem + 255) / 256, 256>>>(out, nc_begin, out_size, 150000.0f);
    }
}

// round 10
// speedup vs baseline: 1.4668x; 1.0637x over previous
#include <cuda_runtime.h>
#include <cuda_bf16.h>
#include <math.h>

typedef unsigned int u32;

// Problem constants (fixed by the dataset)
#define NN 50000
#define EE 800000
#define KK 256     // feature / hidden width
#define CC 40      // n_classes

// ---------------- scratch (static device globals; no allocation) -------------
__device__ float g_Y[(size_t)NN * KK];      // GEMM output buffer
__device__ float g_h[(size_t)NN * KK];      // post-aggregation activations
__device__ int   g_counts[NN];
__device__ int   g_indptr[NN + 1];
__device__ int   g_cursor[NN];
__device__ int   g_srcsorted[EE];
__device__ int   g_blocksums[64];

// bf16 hi/lo transposed weights: Wt[n][k] = W[k][n]  (256x256 each)
__device__ __align__(16) __nv_bfloat16 g_W1hi[65536];
__device__ __align__(16) __nv_bfloat16 g_W1lo[65536];
__device__ __align__(16) __nv_bfloat16 g_W2hi[65536];
__device__ __align__(16) __nv_bfloat16 g_W2lo[65536];

// ---------------- weight prep: W[k][n] -> Wt hi/lo [n][k] --------------------
__global__ void k_prepW(const float* __restrict__ W1, const float* __restrict__ W2) {
    int idx = blockIdx.x * blockDim.x + threadIdx.x;   // 65536
    if (idx >= 65536) return;
    int k = idx & 255, n = idx >> 8;
    float w1 = W1[k * 256 + n];
    __nv_bfloat16 h1 = __float2bfloat16_rn(w1);
    g_W1hi[n * 256 + k] = h1;
    g_W1lo[n * 256 + k] = __float2bfloat16_rn(w1 - __bfloat162float(h1));
    float w2 = W2[k * 256 + n];
    __nv_bfloat16 h2 = __float2bfloat16_rn(w2);
    g_W2hi[n * 256 + k] = h2;
    g_W2lo[n * 256 + k] = __float2bfloat16_rn(w2 - __bfloat162float(h2));
}

// ---------------- pipelined HMMA bf16 hi/lo GEMM -----------------------------
// block 128x128, 8 warps of 32x64, K-chunk 32, double-buffered dynamic SMEM,
// cp.async for B (pre-split bf16), register prefetch for A (fp32->hi/lo).
#define SSTR 40
// element offsets inside dynamic smem (bf16 elements):
//   sA: buf*10240 + hl*5120 + row*SSTR + k          (rows 0..127)
//   sB: 20480 + buf*10240 + hl*5120 + row*SSTR + k  (rows 0..127)
#define SMEM_GEMM_BYTES 81920

__device__ __forceinline__ void mma_bf16(float* c, const u32* a, u32 b0, u32 b1) {
    asm volatile(
        "mma.sync.aligned.m16n8k16.row.col.f32.bf16.bf16.f32 "
        "{%0,%1,%2,%3}, {%4,%5,%6,%7}, {%8,%9}, {%0,%1,%2,%3};\n"
        : "+f"(c[0]), "+f"(c[1]), "+f"(c[2]), "+f"(c[3])
        : "r"(a[0]), "r"(a[1]), "r"(a[2]), "r"(a[3]), "r"(b0), "r"(b1));
}
__device__ __forceinline__ void cp16(u32 smem_byte, const void* gptr) {
    asm volatile("cp.async.cg.shared.global [%0], [%1], 16;\n"
                 :: "r"(smem_byte), "l"(gptr));
}

__global__ void __launch_bounds__(256, 2) k_gemm_mma(const float* __restrict__ A_ext,
                                                     int M, int which) {
    extern __shared__ __nv_bfloat16 dsm[];
    const float* __restrict__ A = which ? g_h : A_ext;
    const __nv_bfloat16* __restrict__ Whi = which ? g_W2hi : g_W1hi;
    const __nv_bfloat16* __restrict__ Wlo = which ? g_W2lo : g_W1lo;

    int tid = threadIdx.x;
    int wid = tid >> 5, lane = tid & 31;
    int g = lane >> 2, tg = lane & 3;
    int wm = (wid & 3) * 32, wn = (wid >> 2) * 64;
    int bm = blockIdx.x * 128, bn = blockIdx.y * 128;

    float acc[2][8][4];
#pragma unroll
    for (int i = 0; i < 2; i++)
#pragma unroll
        for (int j = 0; j < 8; j++)
#pragma unroll
            for (int q = 0; q < 4; q++) acc[i][j][q] = 0.f;

    int lr = tid >> 1;                 // load row (0..127)
    int lc = (tid & 1) * 16;           // load col base (0 or 16)
    bool arow_ok = (bm + lr) < M;
    const float4* ap = (const float4*)(A + (size_t)(bm + lr) * KK + lc);

    u32 smem_base;
    asm("{ .reg .u64 t; cvta.to.shared.u64 t, %1; cvt.u32.u64 %0, t; }"
        : "=r"(smem_base) : "l"((const void*)dsm));

    const __nv_bfloat16* srcBh = Whi + (size_t)(bn + lr) * 256 + lc;
    const __nv_bfloat16* srcBl = Wlo + (size_t)(bn + lr) * 256 + lc;

    // ---- helpers as macros over locals ----
#define CPASYNC_B(kc, buf) do {                                                \
        u32 d0 = smem_base + 40960u + (u32)(buf) * 20480u                      \
                 + (u32)(lr * SSTR + lc) * 2u;                                 \
        cp16(d0,            srcBh + (kc));                                     \
        cp16(d0 + 16u,      srcBh + (kc) + 8);                                 \
        cp16(d0 + 10240u,   srcBl + (kc));                                     \
        cp16(d0 + 10240u + 16u, srcBl + (kc) + 8);                             \
        asm volatile("cp.async.commit_group;\n" ::: "memory");                 \
    } while (0)

#define STORE_A(pa, buf) do {                                                  \
        __nv_bfloat16* pAh = dsm + (buf) * 10240 + lr * SSTR + lc;             \
        __nv_bfloat16* pAl = pAh + 5120;                                       \
        _Pragma("unroll")                                                      \
        for (int j = 0; j < 4; j++) {                                          \
            float4 v = pa[j];                                                  \
            __nv_bfloat16 h0 = __float2bfloat16_rn(v.x);                       \
            __nv_bfloat16 h1 = __float2bfloat16_rn(v.y);                       \
            __nv_bfloat16 h2 = __float2bfloat16_rn(v.z);                       \
            __nv_bfloat16 h3 = __float2bfloat16_rn(v.w);                       \
            __nv_bfloat162 hh01(h0, h1), hh23(h2, h3);                         \
            __nv_bfloat162 ll01(__float2bfloat16_rn(v.x - __bfloat162float(h0)), \
                                __float2bfloat16_rn(v.y - __bfloat162float(h1))); \
            __nv_bfloat162 ll23(__float2bfloat16_rn(v.z - __bfloat162float(h2)), \
                                __float2bfloat16_rn(v.w - __bfloat162float(h3))); \
            *(u32*)&pAh[4 * j]     = *(u32*)&hh01;                             \
            *(u32*)&pAh[4 * j + 2] = *(u32*)&hh23;                             \
            *(u32*)&pAl[4 * j]     = *(u32*)&ll01;                             \
            *(u32*)&pAl[4 * j + 2] = *(u32*)&ll23;                             \
        }                                                                      \
    } while (0)

    // ---- prologue: fill buffer 0 ----
    float4 pa[4];
#pragma unroll
    for (int j = 0; j < 4; j++)
        pa[j] = arow_ok ? ap[j] : make_float4(0.f, 0.f, 0.f, 0.f);
    CPASYNC_B(0, 0);
    STORE_A(pa, 0);
    asm volatile("cp.async.wait_group 0;\n" ::: "memory");
    __syncthreads();

    for (int c = 0; c < 8; c++) {
        int b = c & 1;
        if (c < 7) {
#pragma unroll
            for (int j = 0; j < 4; j++)
                pa[j] = arow_ok ? ap[8 * (c + 1) + j] : make_float4(0.f, 0.f, 0.f, 0.f);
            CPASYNC_B(32 * (c + 1), 1 - b);
        }
        // ---- compute chunk c from buffer b ----
        {
            const __nv_bfloat16* cA = dsm + b * 10240;
            const __nv_bfloat16* cB = dsm + 20480 + b * 10240;
#pragma unroll
            for (int ks = 0; ks < 2; ks++) {
                int kb = ks * 16;
                u32 ahi[2][4], alo[2][4];
#pragma unroll
                for (int mi = 0; mi < 2; mi++) {
                    int r0 = wm + mi * 16 + g;
                    const __nv_bfloat16* ph = cA + r0 * SSTR + kb + tg * 2;
                    ahi[mi][0] = *(const u32*)ph;
                    ahi[mi][1] = *(const u32*)(ph + 8 * SSTR);
                    ahi[mi][2] = *(const u32*)(ph + 8);
                    ahi[mi][3] = *(const u32*)(ph + 8 * SSTR + 8);
                    const __nv_bfloat16* pl = ph + 5120;
                    alo[mi][0] = *(const u32*)pl;
                    alo[mi][1] = *(const u32*)(pl + 8 * SSTR);
                    alo[mi][2] = *(const u32*)(pl + 8);
                    alo[mi][3] = *(const u32*)(pl + 8 * SSTR + 8);
                }
#pragma unroll
                for (int ni = 0; ni < 8; ni++) {
                    int nr = wn + ni * 8 + g;
                    const __nv_bfloat16* pb = cB + nr * SSTR + kb + tg * 2;
                    u32 bh0 = *(const u32*)pb;
                    u32 bh1 = *(const u32*)(pb + 8);
                    u32 bl0 = *(const u32*)(pb + 5120);
                    u32 bl1 = *(const u32*)(pb + 5120 + 8);
#pragma unroll
                    for (int mi = 0; mi < 2; mi++) {
                        mma_bf16(acc[mi][ni], ahi[mi], bh0, bh1);
                        mma_bf16(acc[mi][ni], ahi[mi], bl0, bl1);
                        mma_bf16(acc[mi][ni], alo[mi], bh0, bh1);
                    }
                }
            }
        }
        if (c < 7) {
            STORE_A(pa, 1 - b);
            asm volatile("cp.async.wait_group 0;\n" ::: "memory");
            __syncthreads();
        }
    }

    // ---- epilogue: acc -> g_Y (fp32) ----
#pragma unroll
    for (int mi = 0; mi < 2; mi++) {
        int row0 = bm + wm + mi * 16 + g;
#pragma unroll
        for (int ni = 0; ni < 8; ni++) {
            int col = bn + wn + ni * 8 + tg * 2;
            if (row0 < M)
                *(float2*)&g_Y[(size_t)row0 * KK + col] =
                    make_float2(acc[mi][ni][0], acc[mi][ni][1]);
            if (row0 + 8 < M)
                *(float2*)&g_Y[(size_t)(row0 + 8) * KK + col] =
                    make_float2(acc[mi][ni][2], acc[mi][ni][3]);
        }
    }
#undef CPASYNC_B
#undef STORE_A
}

// ---------------- CSR build --------------------------------------------------
__global__ void k_zero_counts(int n) {
    int i = blockIdx.x * blockDim.x + threadIdx.x;
    if (i < n) g_counts[i] = 0;
}
__global__ void k_hist(const int* __restrict__ edge, int E, int n) {
    int e = blockIdx.x * blockDim.x + threadIdx.x;
    if (e < E) {
        unsigned d = (unsigned)edge[E + e];
        if (d < (unsigned)n) atomicAdd(&g_counts[d], 1);
    }
}
__global__ void k_scan1(int n) {
    __shared__ int sh[1024];
    int i = blockIdx.x * 1024 + threadIdx.x;
    int v = (i < n) ? g_counts[i] : 0;
    sh[threadIdx.x] = v;
    __syncthreads();
    for (int off = 1; off < 1024; off <<= 1) {
        int t = (threadIdx.x >= off) ? sh[threadIdx.x - off] : 0;
        __syncthreads();
        sh[threadIdx.x] += t;
        __syncthreads();
    }
    if (i < n) g_indptr[i] = sh[threadIdx.x];
    if (threadIdx.x == 1023) g_blocksums[blockIdx.x] = sh[1023];
}
__global__ void k_scan2(int nb) {
    __shared__ int sh[64];
    int t = threadIdx.x;
    int v = (t < nb) ? g_blocksums[t] : 0;
    sh[t] = v;
    __syncthreads();
    for (int off = 1; off < 64; off <<= 1) {
        int x = (t >= off) ? sh[t - off] : 0;
        __syncthreads();
        sh[t] += x;
        __syncthreads();
    }
    g_blocksums[t] = sh[t] - v;
}
__global__ void k_scan3(int n, int Etot) {
    int i = blockIdx.x * 1024 + threadIdx.x;
    if (i < n) {
        int excl = g_indptr[i] - g_counts[i] + g_blocksums[blockIdx.x];
        g_indptr[i] = excl;
        g_cursor[i] = excl;
    }
    if (i == 0) g_indptr[n] = Etot;
}
__global__ void k_scatter(const int* __restrict__ edge, int E, int n) {
    int e = blockIdx.x * blockDim.x + threadIdx.x;
    if (e < E) {
        unsigned d = (unsigned)edge[E + e];
        unsigned s = (unsigned)edge[e];
        if (d < (unsigned)n && s < (unsigned)n) {
            int pos = atomicAdd(&g_cursor[d], 1);
            g_srcsorted[pos] = (int)s;
        }
    }
}

// ---------------- fp32 tiled GEMM (layer 3 only, N=40) -----------------------
__global__ void k_gemm(const float* __restrict__ B, int M, int Ncols) {
    const float* __restrict__ A = g_h;
    float* __restrict__ C = g_Y;
    __shared__ __align__(16) float As[16][64];
    __shared__ __align__(16) float Bs[16][64];
    const int K = KK;
    int tid = threadIdx.x;
    int bm = blockIdx.x * 64, bn = blockIdx.y * 64;
    int arow = tid >> 2, acol = (tid & 3) * 4;
    int brow = tid >> 4, bcol = (tid & 15) * 4;
    int ty = tid >> 4, tx = tid & 15;
    float acc[4][4] = {};
    for (int k0 = 0; k0 < K; k0 += 16) {
        float4 av = make_float4(0.f, 0.f, 0.f, 0.f);
        int ar = bm + arow;
        if (ar < M) av = *(const float4*)&A[(size_t)ar * K + k0 + acol];
        As[acol + 0][arow] = av.x;
        As[acol + 1][arow] = av.y;
        As[acol + 2][arow] = av.z;
        As[acol + 3][arow] = av.w;
        float4 bv = make_float4(0.f, 0.f, 0.f, 0.f);
        int bc = bn + bcol;
        if (bc + 3 < Ncols) {
            bv = *(const float4*)&B[(size_t)(k0 + brow) * Ncols + bc];
        } else {
            float t0 = (bc + 0 < Ncols) ? B[(size_t)(k0 + brow) * Ncols + bc + 0] : 0.f;
            float t1 = (bc + 1 < Ncols) ? B[(size_t)(k0 + brow) * Ncols + bc + 1] : 0.f;
            float t2 = (bc + 2 < Ncols) ? B[(size_t)(k0 + brow) * Ncols + bc + 2] : 0.f;
            float t3 = (bc + 3 < Ncols) ? B[(size_t)(k0 + brow) * Ncols + bc + 3] : 0.f;
            bv = make_float4(t0, t1, t2, t3);
        }
        *(float4*)&Bs[brow][bcol] = bv;
        __syncthreads();
#pragma unroll
        for (int kk = 0; kk < 16; kk++) {
            float4 a4 = *(const float4*)&As[kk][ty * 4];
            float4 b4 = *(const float4*)&Bs[kk][tx * 4];
            float a[4] = {a4.x, a4.y, a4.z, a4.w};
            float b[4] = {b4.x, b4.y, b4.z, b4.w};
#pragma unroll
            for (int i = 0; i < 4; i++)
#pragma unroll
                for (int j = 0; j < 4; j++) acc[i][j] += a[i] * b[j];
        }
        __syncthreads();
    }
#pragma unroll
    for (int i = 0; i < 4; i++) {
        int r = bm + ty * 4 + i;
        if (r >= M) continue;
#pragma unroll
        for (int j = 0; j < 4; j++) {
            int c = bn + tx * 4 + j;
            if (c < Ncols) C[(size_t)r * Ncols + c] = acc[i][j];
        }
    }
}

// ---------------- aggregation (256-wide) + bias + relu -----------------------
__global__ void k_agg_relu(const float* __restrict__ bias) {
    const float* __restrict__ Y = g_Y;
    __shared__ int sidx[64];
    int node = blockIdx.x;
    int start = g_indptr[node], end = g_indptr[node + 1];
    float acc = 0.f;
    for (int base = start; base < end; base += 64) {
        int m = end - base;
        if (m > 64) m = 64;
        if (threadIdx.x < m) sidx[threadIdx.x] = g_srcsorted[base + threadIdx.x];
        __syncthreads();
#pragma unroll 4
        for (int i = 0; i < m; i++) {
            acc += Y[(size_t)sidx[i] * KK + threadIdx.x];
        }
        __syncthreads();
    }
    g_h[(size_t)node * KK + threadIdx.x] = fmaxf(acc + bias[threadIdx.x], 0.f);
}

// ---------------- aggregation (40-wide) + bias + log_softmax -----------------
__global__ void k_agg_lsm(const float* __restrict__ b3, float* __restrict__ out, int n) {
    const float* __restrict__ Y3 = g_Y;
    int warp = (blockIdx.x * blockDim.x + threadIdx.x) >> 5;
    int lane = threadIdx.x & 31;
    if (warp >= n) return;
    int start = g_indptr[warp], end = g_indptr[warp + 1];
    float acc0 = 0.f, acc1 = 0.f;
    for (int e = start; e < end; e++) {
        int s = g_srcsorted[e];
        acc0 += Y3[(size_t)s * CC + lane];
        if (lane < 8) acc1 += Y3[(size_t)s * CC + 32 + lane];
    }
    float v0 = acc0 + b3[lane];
    float v1 = (lane < 8) ? (acc1 + b3[32 + lane]) : -1e30f;
    float m = fmaxf(v0, v1);
#pragma unroll
    for (int off = 16; off; off >>= 1) m = fmaxf(m, __shfl_xor_sync(0xffffffffu, m, off));
    float s0 = expf(v0 - m) + ((lane < 8) ? expf(v1 - m) : 0.f);
#pragma unroll
    for (int off = 16; off; off >>= 1) s0 += __shfl_xor_sync(0xffffffffu, s0, off);
    float lse = m + logf(s0);
    out[(size_t)warp * CC + lane] = v0 - lse;
    if (lane < 8) out[(size_t)warp * CC + 32 + lane] = v1 - lse;
}

// ---------------- tail: node_count scalar(s) ---------------------------------
__global__ void k_tail(float* __restrict__ out, int begin, int total, float val) {
    int i = begin + blockIdx.x * blockDim.x + threadIdx.x;
    if (i < total) out[i] = val;
}

// ---------------- launch -----------------------------------------------------
extern "C" void kernel_launch(void* const* d_in, const int* in_sizes, int n_in,
                              void* d_out, int out_size) {
    const float* features = (const float*)d_in[0];
    const int*   edge     = (const int*)d_in[1];   // int32 (JAX x64 disabled)
    const float* W1 = (const float*)d_in[4];
    const float* b1 = (const float*)d_in[5];
    const float* W2 = (const float*)d_in[6];
    const float* b2 = (const float*)d_in[7];
    const float* W3 = (const float*)d_in[8];
    const float* b3 = (const float*)d_in[9];
    float* out = (float*)d_out;

    int n = in_sizes[0] / KK;      // 50000
    int E = in_sizes[1] / 2;       // 800000

    cudaFuncSetAttribute(k_gemm_mma, cudaFuncAttributeMaxDynamicSharedMemorySize,
                         SMEM_GEMM_BYTES);

    // ---- weight prep + CSR by dst ----
    k_prepW<<<256, 256>>>(W1, W2);
    k_zero_counts<<<(n + 255) / 256, 256>>>(n);
    k_hist<<<(E + 255) / 256, 256>>>(edge, E, n);
    int NB = (n + 1023) / 1024;
    k_scan1<<<NB, 1024>>>(n);
    k_scan2<<<1, 64>>>(NB);
    k_scan3<<<NB, 1024>>>(n, E);
    k_scatter<<<(E + 255) / 256, 256>>>(edge, E, n);

    dim3 gmm((n + 127) / 128, 2);

    // ---- layer 1: Y = X @ W1 (HMMA) ; h = relu(agg(Y) + b1) ----
    k_gemm_mma<<<gmm, 256, SMEM_GEMM_BYTES>>>(features, n, 0);
    k_agg_relu<<<n, 256>>>(b1);

    // ---- layer 2: Y = h @ W2 (HMMA) ; h = relu(agg(Y) + b2) ----
    k_gemm_mma<<<gmm, 256, SMEM_GEMM_BYTES>>>(nullptr, n, 1);
    k_agg_relu<<<n, 256>>>(b2);

    // ---- layer 3: Y3 = h @ W3 (N x 40, SIMT) ; out = log_softmax(agg+b3) ----
    dim3 g40((n + 63) / 64, (CC + 63) / 64);
    k_gemm<<<g40, 256>>>(W3, n, CC);
    k_agg_lsm<<<(n * 32 + 255) / 256, 256>>>(b3, out, n);

    // ---- node_count tail ----
    int nc_begin = n * CC;
    if (out_size > nc_begin) {
        int rem = out_size - nc_begin;
        k_tail<<<(rem + 255) / 256, 256>>>(out, nc_begin, out_size, 150000.0f);
    }
}

// round 11
// speedup vs baseline: 1.6481x; 1.1236x over previous
#include <cuda_runtime.h>
#include <cuda_bf16.h>
#include <math.h>

typedef unsigned int u32;

// Problem constants (fixed by the dataset)
#define NN 50000
#define EE 800000
#define KK 256     // feature / hidden width
#define CC 40      // n_classes

// ---------------- scratch (static device globals; no allocation) -------------
__device__ float g_Y[(size_t)NN * KK];      // GEMM output buffer
__device__ float g_h[(size_t)NN * KK];      // post-aggregation activations
__device__ int   g_counts[NN];
__device__ int   g_indptr[NN + 1];
__device__ int   g_cursor[NN];
__device__ int   g_srcsorted[EE];
__device__ int   g_blocksums[64];

// bf16 hi/lo transposed weights: Wt[n][k] = W[k][n]
__device__ __align__(16) __nv_bfloat16 g_W1hi[65536];
__device__ __align__(16) __nv_bfloat16 g_W1lo[65536];
__device__ __align__(16) __nv_bfloat16 g_W2hi[65536];
__device__ __align__(16) __nv_bfloat16 g_W2lo[65536];
__device__ __align__(16) __nv_bfloat16 g_W3hi[64 * 256];   // padded 40->64 rows
__device__ __align__(16) __nv_bfloat16 g_W3lo[64 * 256];

// ---------------- weight prep ------------------------------------------------
__global__ void k_prepW(const float* __restrict__ W1, const float* __restrict__ W2) {
    int idx = blockIdx.x * blockDim.x + threadIdx.x;   // 65536
    if (idx >= 65536) return;
    int k = idx & 255, n = idx >> 8;
    float w1 = W1[k * 256 + n];
    __nv_bfloat16 h1 = __float2bfloat16_rn(w1);
    g_W1hi[n * 256 + k] = h1;
    g_W1lo[n * 256 + k] = __float2bfloat16_rn(w1 - __bfloat162float(h1));
    float w2 = W2[k * 256 + n];
    __nv_bfloat16 h2 = __float2bfloat16_rn(w2);
    g_W2hi[n * 256 + k] = h2;
    g_W2lo[n * 256 + k] = __float2bfloat16_rn(w2 - __bfloat162float(h2));
}
__global__ void k_prepW3(const float* __restrict__ W3) {
    int idx = blockIdx.x * blockDim.x + threadIdx.x;   // 16384
    if (idx >= 64 * 256) return;
    int k = idx & 255, n = idx >> 8;                   // n 0..63
    float w = (n < CC) ? W3[k * CC + n] : 0.f;
    __nv_bfloat16 h = __float2bfloat16_rn(w);
    g_W3hi[n * 256 + k] = h;
    g_W3lo[n * 256 + k] = __float2bfloat16_rn(w - __bfloat162float(h));
}

// ---------------- pipelined HMMA bf16 hi/lo GEMMs ----------------------------
#define SSTR 40
#define SMEM_GEMM_BYTES 81920
#define SMEM_GEMM3_BYTES 61440

__device__ __forceinline__ void mma_bf16(float* c, const u32* a, u32 b0, u32 b1) {
    asm volatile(
        "mma.sync.aligned.m16n8k16.row.col.f32.bf16.bf16.f32 "
        "{%0,%1,%2,%3}, {%4,%5,%6,%7}, {%8,%9}, {%0,%1,%2,%3};\n"
        : "+f"(c[0]), "+f"(c[1]), "+f"(c[2]), "+f"(c[3])
        : "r"(a[0]), "r"(a[1]), "r"(a[2]), "r"(a[3]), "r"(b0), "r"(b1));
}
__device__ __forceinline__ void cp16(u32 smem_byte, const void* gptr) {
    asm volatile("cp.async.cg.shared.global [%0], [%1], 16;\n"
                 :: "r"(smem_byte), "l"(gptr));
}

#define STORE_A(pa, buf) do {                                                  \
        __nv_bfloat16* pAh = dsm + (buf) * 10240 + lr * SSTR + lc;             \
        __nv_bfloat16* pAl = pAh + 5120;                                       \
        _Pragma("unroll")                                                      \
        for (int j = 0; j < 4; j++) {                                          \
            float4 v = pa[j];                                                  \
            __nv_bfloat16 h0 = __float2bfloat16_rn(v.x);                       \
            __nv_bfloat16 h1 = __float2bfloat16_rn(v.y);                       \
            __nv_bfloat16 h2 = __float2bfloat16_rn(v.z);                       \
            __nv_bfloat16 h3 = __float2bfloat16_rn(v.w);                       \
            __nv_bfloat162 hh01(h0, h1), hh23(h2, h3);                         \
            __nv_bfloat162 ll01(__float2bfloat16_rn(v.x - __bfloat162float(h0)), \
                                __float2bfloat16_rn(v.y - __bfloat162float(h1))); \
            __nv_bfloat162 ll23(__float2bfloat16_rn(v.z - __bfloat162float(h2)), \
                                __float2bfloat16_rn(v.w - __bfloat162float(h3))); \
            *(u32*)&pAh[4 * j]     = *(u32*)&hh01;                             \
            *(u32*)&pAh[4 * j + 2] = *(u32*)&hh23;                             \
            *(u32*)&pAl[4 * j]     = *(u32*)&ll01;                             \
            *(u32*)&pAl[4 * j + 2] = *(u32*)&ll23;                             \
        }                                                                      \
    } while (0)

// ---- layers 1/2: 128x128 tile, 8 warps of 32x64 -----------------------------
__global__ void __launch_bounds__(256, 2) k_gemm_mma(const float* __restrict__ A_ext,
                                                     int M, int which) {
    extern __shared__ __nv_bfloat16 dsm[];
    const float* __restrict__ A = which ? g_h : A_ext;
    const __nv_bfloat16* __restrict__ Whi = which ? g_W2hi : g_W1hi;
    const __nv_bfloat16* __restrict__ Wlo = which ? g_W2lo : g_W1lo;

    int tid = threadIdx.x;
    int wid = tid >> 5, lane = tid & 31;
    int g = lane >> 2, tg = lane & 3;
    int wm = (wid & 3) * 32, wn = (wid >> 2) * 64;
    int bm = blockIdx.x * 128, bn = blockIdx.y * 128;

    float acc[2][8][4];
#pragma unroll
    for (int i = 0; i < 2; i++)
#pragma unroll
        for (int j = 0; j < 8; j++)
#pragma unroll
            for (int q = 0; q < 4; q++) acc[i][j][q] = 0.f;

    int lr = tid >> 1;
    int lc = (tid & 1) * 16;
    bool arow_ok = (bm + lr) < M;
    const float4* ap = (const float4*)(A + (size_t)(bm + lr) * KK + lc);

    u32 smem_base;
    asm("{ .reg .u64 t; cvta.to.shared.u64 t, %1; cvt.u32.u64 %0, t; }"
        : "=r"(smem_base) : "l"((const void*)dsm));

    const __nv_bfloat16* srcBh = Whi + (size_t)(bn + lr) * 256 + lc;
    const __nv_bfloat16* srcBl = Wlo + (size_t)(bn + lr) * 256 + lc;

#define CPASYNC_B(kc, buf) do {                                                \
        u32 d0 = smem_base + 40960u + (u32)(buf) * 20480u                      \
                 + (u32)(lr * SSTR + lc) * 2u;                                 \
        cp16(d0,            srcBh + (kc));                                     \
        cp16(d0 + 16u,      srcBh + (kc) + 8);                                 \
        cp16(d0 + 10240u,   srcBl + (kc));                                     \
        cp16(d0 + 10240u + 16u, srcBl + (kc) + 8);                             \
        asm volatile("cp.async.commit_group;\n" ::: "memory");                 \
    } while (0)

    float4 pa[4];
#pragma unroll
    for (int j = 0; j < 4; j++)
        pa[j] = arow_ok ? ap[j] : make_float4(0.f, 0.f, 0.f, 0.f);
    CPASYNC_B(0, 0);
    STORE_A(pa, 0);
    asm volatile("cp.async.wait_group 0;\n" ::: "memory");
    __syncthreads();

    for (int c = 0; c < 8; c++) {
        int b = c & 1;
        if (c < 7) {
#pragma unroll
            for (int j = 0; j < 4; j++)
                pa[j] = arow_ok ? ap[8 * (c + 1) + j] : make_float4(0.f, 0.f, 0.f, 0.f);
            CPASYNC_B(32 * (c + 1), 1 - b);
        }
        {
            const __nv_bfloat16* cA = dsm + b * 10240;
            const __nv_bfloat16* cB = dsm + 20480 + b * 10240;
#pragma unroll
            for (int ks = 0; ks < 2; ks++) {
                int kb = ks * 16;
                u32 ahi[2][4], alo[2][4];
#pragma unroll
                for (int mi = 0; mi < 2; mi++) {
                    int r0 = wm + mi * 16 + g;
                    const __nv_bfloat16* ph = cA + r0 * SSTR + kb + tg * 2;
                    ahi[mi][0] = *(const u32*)ph;
                    ahi[mi][1] = *(const u32*)(ph + 8 * SSTR);
                    ahi[mi][2] = *(const u32*)(ph + 8);
                    ahi[mi][3] = *(const u32*)(ph + 8 * SSTR + 8);
                    const __nv_bfloat16* pl = ph + 5120;
                    alo[mi][0] = *(const u32*)pl;
                    alo[mi][1] = *(const u32*)(pl + 8 * SSTR);
                    alo[mi][2] = *(const u32*)(pl + 8);
                    alo[mi][3] = *(const u32*)(pl + 8 * SSTR + 8);
                }
#pragma unroll
                for (int ni = 0; ni < 8; ni++) {
                    int nr = wn + ni * 8 + g;
                    const __nv_bfloat16* pb = cB + nr * SSTR + kb + tg * 2;
                    u32 bh0 = *(const u32*)pb;
                    u32 bh1 = *(const u32*)(pb + 8);
                    u32 bl0 = *(const u32*)(pb + 5120);
                    u32 bl1 = *(const u32*)(pb + 5120 + 8);
#pragma unroll
                    for (int mi = 0; mi < 2; mi++) {
                        mma_bf16(acc[mi][ni], ahi[mi], bh0, bh1);
                        mma_bf16(acc[mi][ni], ahi[mi], bl0, bl1);
                        mma_bf16(acc[mi][ni], alo[mi], bh0, bh1);
                    }
                }
            }
        }
        if (c < 7) {
            STORE_A(pa, 1 - b);
            asm volatile("cp.async.wait_group 0;\n" ::: "memory");
            __syncthreads();
        }
    }

#pragma unroll
    for (int mi = 0; mi < 2; mi++) {
        int row0 = bm + wm + mi * 16 + g;
#pragma unroll
        for (int ni = 0; ni < 8; ni++) {
            int col = bn + wn + ni * 8 + tg * 2;
            if (row0 < M)
                *(float2*)&g_Y[(size_t)row0 * KK + col] =
                    make_float2(acc[mi][ni][0], acc[mi][ni][1]);
            if (row0 + 8 < M)
                *(float2*)&g_Y[(size_t)(row0 + 8) * KK + col] =
                    make_float2(acc[mi][ni][2], acc[mi][ni][3]);
        }
    }
#undef CPASYNC_B
}

// ---- layer 3: 128x64 tile, 8 warps of 32x32, writes g_Y[M][40] --------------
__global__ void __launch_bounds__(256, 2) k_gemm_mma3(int M) {
    extern __shared__ __nv_bfloat16 dsm[];
    const float* __restrict__ A = g_h;

    int tid = threadIdx.x;
    int wid = tid >> 5, lane = tid & 31;
    int g = lane >> 2, tg = lane & 3;
    int wm = (wid & 3) * 32, wn = (wid >> 2) * 32;
    int bm = blockIdx.x * 128;

    float acc[2][4][4];
#pragma unroll
    for (int i = 0; i < 2; i++)
#pragma unroll
        for (int j = 0; j < 4; j++)
#pragma unroll
            for (int q = 0; q < 4; q++) acc[i][j][q] = 0.f;

    int lr = tid >> 1;
    int lc = (tid & 1) * 16;
    bool arow_ok = (bm + lr) < M;
    const float4* ap = (const float4*)(A + (size_t)(bm + lr) * KK + lc);

    u32 smem_base;
    asm("{ .reg .u64 t; cvta.to.shared.u64 t, %1; cvt.u32.u64 %0, t; }"
        : "=r"(smem_base) : "l"((const void*)dsm));

    const __nv_bfloat16* srcBh = g_W3hi + (size_t)lr * 256 + lc;
    const __nv_bfloat16* srcBl = g_W3lo + (size_t)lr * 256 + lc;

    // smem element layout: sA: buf*10240 + hl*5120 + row*40 + k
    //                      sB: 20480 + buf*5120 + hl*2560 + row*40 + k (rows 0..63)
#define CPASYNC_B3(kc, buf) do {                                               \
        if (lr < 64) {                                                         \
            u32 d0 = smem_base + 40960u + (u32)(buf) * 10240u                  \
                     + (u32)(lr * SSTR + lc) * 2u;                             \
            cp16(d0,           srcBh + (kc));                                  \
            cp16(d0 + 16u,     srcBh + (kc) + 8);                              \
            cp16(d0 + 5120u,   srcBl + (kc));                                  \
            cp16(d0 + 5120u + 16u, srcBl + (kc) + 8);                          \
        }                                                                      \
        asm volatile("cp.async.commit_group;\n" ::: "memory");                 \
    } while (0)

    float4 pa[4];
#pragma unroll
    for (int j = 0; j < 4; j++)
        pa[j] = arow_ok ? ap[j] : make_float4(0.f, 0.f, 0.f, 0.f);
    CPASYNC_B3(0, 0);
    STORE_A(pa, 0);
    asm volatile("cp.async.wait_group 0;\n" ::: "memory");
    __syncthreads();

    for (int c = 0; c < 8; c++) {
        int b = c & 1;
        if (c < 7) {
#pragma unroll
            for (int j = 0; j < 4; j++)
                pa[j] = arow_ok ? ap[8 * (c + 1) + j] : make_float4(0.f, 0.f, 0.f, 0.f);
            CPASYNC_B3(32 * (c + 1), 1 - b);
        }
        {
            const __nv_bfloat16* cA = dsm + b * 10240;
            const __nv_bfloat16* cB = dsm + 20480 + b * 5120;
#pragma unroll
            for (int ks = 0; ks < 2; ks++) {
                int kb = ks * 16;
                u32 ahi[2][4], alo[2][4];
#pragma unroll
                for (int mi = 0; mi < 2; mi++) {
                    int r0 = wm + mi * 16 + g;
                    const __nv_bfloat16* ph = cA + r0 * SSTR + kb + tg * 2;
                    ahi[mi][0] = *(const u32*)ph;
                    ahi[mi][1] = *(const u32*)(ph + 8 * SSTR);
                    ahi[mi][2] = *(const u32*)(ph + 8);
                    ahi[mi][3] = *(const u32*)(ph + 8 * SSTR + 8);
                    const __nv_bfloat16* pl = ph + 5120;
                    alo[mi][0] = *(const u32*)pl;
                    alo[mi][1] = *(const u32*)(pl + 8 * SSTR);
                    alo[mi][2] = *(const u32*)(pl + 8);
                    alo[mi][3] = *(const u32*)(pl + 8 * SSTR + 8);
                }
#pragma unroll
                for (int ni = 0; ni < 4; ni++) {
                    int nr = wn + ni * 8 + g;
                    const __nv_bfloat16* pb = cB + nr * SSTR + kb + tg * 2;
                    u32 bh0 = *(const u32*)pb;
                    u32 bh1 = *(const u32*)(pb + 8);
                    u32 bl0 = *(const u32*)(pb + 2560);
                    u32 bl1 = *(const u32*)(pb + 2560 + 8);
#pragma unroll
                    for (int mi = 0; mi < 2; mi++) {
                        mma_bf16(acc[mi][ni], ahi[mi], bh0, bh1);
                        mma_bf16(acc[mi][ni], ahi[mi], bl0, bl1);
                        mma_bf16(acc[mi][ni], alo[mi], bh0, bh1);
                    }
                }
            }
        }
        if (c < 7) {
            STORE_A(pa, 1 - b);
            asm volatile("cp.async.wait_group 0;\n" ::: "memory");
            __syncthreads();
        }
    }

#pragma unroll
    for (int mi = 0; mi < 2; mi++) {
        int row0 = bm + wm + mi * 16 + g;
#pragma unroll
        for (int ni = 0; ni < 4; ni++) {
            int col = wn + ni * 8 + tg * 2;
            if (col < CC) {
                if (row0 < M)
                    *(float2*)&g_Y[(size_t)row0 * CC + col] =
                        make_float2(acc[mi][ni][0], acc[mi][ni][1]);
                if (row0 + 8 < M)
                    *(float2*)&g_Y[(size_t)(row0 + 8) * CC + col] =
                        make_float2(acc[mi][ni][2], acc[mi][ni][3]);
            }
        }
    }
#undef CPASYNC_B3
}

// ---------------- CSR build --------------------------------------------------
__global__ void k_zero_counts(int n) {
    int i = blockIdx.x * blockDim.x + threadIdx.x;
    if (i < n) g_counts[i] = 0;
}
__global__ void k_hist(const int* __restrict__ edge, int E, int n) {
    int e = blockIdx.x * blockDim.x + threadIdx.x;
    if (e < E) {
        unsigned d = (unsigned)edge[E + e];
        if (d < (unsigned)n) atomicAdd(&g_counts[d], 1);
    }
}
__global__ void k_scan1(int n) {
    __shared__ int sh[1024];
    int i = blockIdx.x * 1024 + threadIdx.x;
    int v = (i < n) ? g_counts[i] : 0;
    sh[threadIdx.x] = v;
    __syncthreads();
    for (int off = 1; off < 1024; off <<= 1) {
        int t = (threadIdx.x >= off) ? sh[threadIdx.x - off] : 0;
        __syncthreads();
        sh[threadIdx.x] += t;
        __syncthreads();
    }
    if (i < n) g_indptr[i] = sh[threadIdx.x];
    if (threadIdx.x == 1023) g_blocksums[blockIdx.x] = sh[1023];
}
__global__ void k_scan2(int nb) {
    __shared__ int sh[64];
    int t = threadIdx.x;
    int v = (t < nb) ? g_blocksums[t] : 0;
    sh[t] = v;
    __syncthreads();
    for (int off = 1; off < 64; off <<= 1) {
        int x = (t >= off) ? sh[t - off] : 0;
        __syncthreads();
        sh[t] += x;
        __syncthreads();
    }
    g_blocksums[t] = sh[t] - v;
}
__global__ void k_scan3(int n, int Etot) {
    int i = blockIdx.x * 1024 + threadIdx.x;
    if (i < n) {
        int excl = g_indptr[i] - g_counts[i] + g_blocksums[blockIdx.x];
        g_indptr[i] = excl;
        g_cursor[i] = excl;
    }
    if (i == 0) g_indptr[n] = Etot;
}
__global__ void k_scatter(const int* __restrict__ edge, int E, int n) {
    int e = blockIdx.x * blockDim.x + threadIdx.x;
    if (e < E) {
        unsigned d = (unsigned)edge[E + e];
        unsigned s = (unsigned)edge[e];
        if (d < (unsigned)n && s < (unsigned)n) {
            int pos = atomicAdd(&g_cursor[d], 1);
            g_srcsorted[pos] = (int)s;
        }
    }
}

// ---------------- aggregation (256-wide) + bias + relu -----------------------
__global__ void k_agg_relu(const float* __restrict__ bias) {
    const float* __restrict__ Y = g_Y;
    __shared__ int sidx[64];
    int node = blockIdx.x;
    int start = g_indptr[node], end = g_indptr[node + 1];
    float acc = 0.f;
    for (int base = start; base < end; base += 64) {
        int m = end - base;
        if (m > 64) m = 64;
        if (threadIdx.x < m) sidx[threadIdx.x] = g_srcsorted[base + threadIdx.x];
        __syncthreads();
#pragma unroll 4
        for (int i = 0; i < m; i++) {
            acc += Y[(size_t)sidx[i] * KK + threadIdx.x];
        }
        __syncthreads();
    }
    g_h[(size_t)node * KK + threadIdx.x] = fmaxf(acc + bias[threadIdx.x], 0.f);
}

// ---------------- aggregation (40-wide) + bias + log_softmax -----------------
__global__ void k_agg_lsm(const float* __restrict__ b3, float* __restrict__ out, int n) {
    const float* __restrict__ Y3 = g_Y;
    int warp = (blockIdx.x * blockDim.x + threadIdx.x) >> 5;
    int lane = threadIdx.x & 31;
    if (warp >= n) return;
    int start = g_indptr[warp], end = g_indptr[warp + 1];
    float acc0 = 0.f, acc1 = 0.f;
    for (int e = start; e < end; e++) {
        int s = g_srcsorted[e];
        acc0 += Y3[(size_t)s * CC + lane];
        if (lane < 8) acc1 += Y3[(size_t)s * CC + 32 + lane];
    }
    float v0 = acc0 + b3[lane];
    float v1 = (lane < 8) ? (acc1 + b3[32 + lane]) : -1e30f;
    float m = fmaxf(v0, v1);
#pragma unroll
    for (int off = 16; off; off >>= 1) m = fmaxf(m, __shfl_xor_sync(0xffffffffu, m, off));
    float s0 = expf(v0 - m) + ((lane < 8) ? expf(v1 - m) : 0.f);
#pragma unroll
    for (int off = 16; off; off >>= 1) s0 += __shfl_xor_sync(0xffffffffu, s0, off);
    float lse = m + logf(s0);
    out[(size_t)warp * CC + lane] = v0 - lse;
    if (lane < 8) out[(size_t)warp * CC + 32 + lane] = v1 - lse;
}

// ---------------- tail: node_count scalar(s) ---------------------------------
__global__ void k_tail(float* __restrict__ out, int begin, int total, float val) {
    int i = begin + blockIdx.x * blockDim.x + threadIdx.x;
    if (i < total) out[i] = val;
}

// ---------------- launch -----------------------------------------------------
extern "C" void kernel_launch(void* const* d_in, const int* in_sizes, int n_in,
                              void* d_out, int out_size) {
    const float* features = (const float*)d_in[0];
    const int*   edge     = (const int*)d_in[1];   // int32 (JAX x64 disabled)
    const float* W1 = (const float*)d_in[4];
    const float* b1 = (const float*)d_in[5];
    const float* W2 = (const float*)d_in[6];
    const float* b2 = (const float*)d_in[7];
    const float* W3 = (const float*)d_in[8];
    const float* b3 = (const float*)d_in[9];
    float* out = (float*)d_out;

    int n = in_sizes[0] / KK;      // 50000
    int E = in_sizes[1] / 2;       // 800000

    cudaFuncSetAttribute(k_gemm_mma, cudaFuncAttributeMaxDynamicSharedMemorySize,
                         SMEM_GEMM_BYTES);
    cudaFuncSetAttribute(k_gemm_mma3, cudaFuncAttributeMaxDynamicSharedMemorySize,
                         SMEM_GEMM3_BYTES);

    // side stream + events, created once (first call is the eager correctness run)
    static cudaStream_t s2 = nullptr;
    static cudaEvent_t ev0 = nullptr, ev1 = nullptr;
    if (!s2) {
        cudaStreamCreateWithFlags(&s2, cudaStreamNonBlocking);
        cudaEventCreateWithFlags(&ev0, cudaEventDisableTiming);
        cudaEventCreateWithFlags(&ev1, cudaEventDisableTiming);
    }

    // ---- fork: CSR build + W3 prep on s2, overlapped with prepW + GEMM1 ----
    cudaEventRecord(ev0, 0);
    cudaStreamWaitEvent(s2, ev0, 0);

    k_prepW3<<<64, 256, 0, s2>>>(W3);
    k_zero_counts<<<(n + 255) / 256, 256, 0, s2>>>(n);
    k_hist<<<(E + 255) / 256, 256, 0, s2>>>(edge, E, n);
    int NB = (n + 1023) / 1024;
    k_scan1<<<NB, 1024, 0, s2>>>(n);
    k_scan2<<<1, 64, 0, s2>>>(NB);
    k_scan3<<<NB, 1024, 0, s2>>>(n, E);
    k_scatter<<<(E + 255) / 256, 256, 0, s2>>>(edge, E, n);
    cudaEventRecord(ev1, s2);

    // ---- main stream: weights + GEMM1 ----
    k_prepW<<<256, 256>>>(W1, W2);
    dim3 gmm((n + 127) / 128, 2);
    k_gemm_mma<<<gmm, 256, SMEM_GEMM_BYTES>>>(features, n, 0);

    // join: aggregation needs the CSR
    cudaStreamWaitEvent(0, ev1, 0);

    // ---- layer 1 agg ; layer 2 ; layer 3 ----
    k_agg_relu<<<n, 256>>>(b1);
    k_gemm_mma<<<gmm, 256, SMEM_GEMM_BYTES>>>(nullptr, n, 1);
    k_agg_relu<<<n, 256>>>(b2);
    k_gemm_mma3<<<(n + 127) / 128, 256, SMEM_GEMM3_BYTES>>>(n);
    k_agg_lsm<<<(n * 32 + 255) / 256, 256>>>(b3, out, n);

    // ---- node_count tail ----
    int nc_begin = n * CC;
    if (out_size > nc_begin) {
        int rem = out_size - nc_begin;
        k_tail<<<(rem + 255) / 256, 256>>>(out, nc_begin, out_size, 150000.0f);
    }
}

// round 12
// speedup vs baseline: 1.7224x; 1.0451x over previous
#include <cuda_runtime.h>
#include <cuda_bf16.h>
#include <math.h>

typedef unsigned int u32;

// Problem constants (fixed by the dataset)
#define NN 50000
#define EE 800000
#define KK 256     // feature / hidden width
#define CC 40      // n_classes

// ---------------- scratch (static device globals; no allocation) -------------
__device__ float g_Y[(size_t)NN * KK];      // GEMM output buffer
__device__ float g_h[(size_t)NN * KK];      // layer-1 activations
__device__ float g_h2[(size_t)NN * KK];     // layer-2 activations
__device__ int   g_counts[NN];
__device__ int   g_indptr[NN + 1];
__device__ int   g_cursor[NN];
__device__ int   g_srcsorted[EE];
__device__ int   g_blocksums[64];

// bf16 hi/lo transposed weights: Wt[n][k] = W[k][n]
__device__ __align__(16) __nv_bfloat16 g_W1hi[65536];
__device__ __align__(16) __nv_bfloat16 g_W1lo[65536];
__device__ __align__(16) __nv_bfloat16 g_W2hi[65536];
__device__ __align__(16) __nv_bfloat16 g_W2lo[65536];
__device__ __align__(16) __nv_bfloat16 g_W3hi[64 * 256];   // padded 40->64 rows
__device__ __align__(16) __nv_bfloat16 g_W3lo[64 * 256];

// ---------------- weight prep ------------------------------------------------
__global__ void k_prepW(const float* __restrict__ W1, const float* __restrict__ W2) {
    int idx = blockIdx.x * blockDim.x + threadIdx.x;   // 65536
    if (idx >= 65536) return;
    int k = idx & 255, n = idx >> 8;
    float w1 = W1[k * 256 + n];
    __nv_bfloat16 h1 = __float2bfloat16_rn(w1);
    g_W1hi[n * 256 + k] = h1;
    g_W1lo[n * 256 + k] = __float2bfloat16_rn(w1 - __bfloat162float(h1));
    float w2 = W2[k * 256 + n];
    __nv_bfloat16 h2 = __float2bfloat16_rn(w2);
    g_W2hi[n * 256 + k] = h2;
    g_W2lo[n * 256 + k] = __float2bfloat16_rn(w2 - __bfloat162float(h2));
}
__global__ void k_prepW3(const float* __restrict__ W3) {
    int idx = blockIdx.x * blockDim.x + threadIdx.x;   // 16384
    if (idx >= 64 * 256) return;
    int k = idx & 255, n = idx >> 8;                   // n 0..63
    float w = (n < CC) ? W3[k * CC + n] : 0.f;
    __nv_bfloat16 h = __float2bfloat16_rn(w);
    g_W3hi[n * 256 + k] = h;
    g_W3lo[n * 256 + k] = __float2bfloat16_rn(w - __bfloat162float(h));
}

// ---------------- pipelined HMMA bf16 hi/lo GEMMs ----------------------------
#define SSTR 40
#define SMEM_GEMM_BYTES 81920
#define SMEM_GEMM3_BYTES 61440

__device__ __forceinline__ void mma_bf16(float* c, const u32* a, u32 b0, u32 b1) {
    asm volatile(
        "mma.sync.aligned.m16n8k16.row.col.f32.bf16.bf16.f32 "
        "{%0,%1,%2,%3}, {%4,%5,%6,%7}, {%8,%9}, {%0,%1,%2,%3};\n"
        : "+f"(c[0]), "+f"(c[1]), "+f"(c[2]), "+f"(c[3])
        : "r"(a[0]), "r"(a[1]), "r"(a[2]), "r"(a[3]), "r"(b0), "r"(b1));
}
__device__ __forceinline__ void cp16(u32 smem_byte, const void* gptr) {
    asm volatile("cp.async.cg.shared.global [%0], [%1], 16;\n"
                 :: "r"(smem_byte), "l"(gptr));
}

#define STORE_A(pa, buf) do {                                                  \
        __nv_bfloat16* pAh = dsm + (buf) * 10240 + lr * SSTR + lc;             \
        __nv_bfloat16* pAl = pAh + 5120;                                       \
        _Pragma("unroll")                                                      \
        for (int j = 0; j < 4; j++) {                                          \
            float4 v = pa[j];                                                  \
            __nv_bfloat16 h0 = __float2bfloat16_rn(v.x);                       \
            __nv_bfloat16 h1 = __float2bfloat16_rn(v.y);                       \
            __nv_bfloat16 h2 = __float2bfloat16_rn(v.z);                       \
            __nv_bfloat16 h3 = __float2bfloat16_rn(v.w);                       \
            __nv_bfloat162 hh01(h0, h1), hh23(h2, h3);                         \
            __nv_bfloat162 ll01(__float2bfloat16_rn(v.x - __bfloat162float(h0)), \
                                __float2bfloat16_rn(v.y - __bfloat162float(h1))); \
            __nv_bfloat162 ll23(__float2bfloat16_rn(v.z - __bfloat162float(h2)), \
                                __float2bfloat16_rn(v.w - __bfloat162float(h3))); \
            *(u32*)&pAh[4 * j]     = *(u32*)&hh01;                             \
            *(u32*)&pAh[4 * j + 2] = *(u32*)&hh23;                             \
            *(u32*)&pAl[4 * j]     = *(u32*)&ll01;                             \
            *(u32*)&pAl[4 * j + 2] = *(u32*)&ll23;                             \
        }                                                                      \
    } while (0)

// ---- layers 1/2: 128x128 tile, 8 warps of 32x64; bn = column base ----------
__global__ void __launch_bounds__(256, 2) k_gemm_mma(const float* __restrict__ A_ext,
                                                     int M, int which, int bn) {
    extern __shared__ __nv_bfloat16 dsm[];
    const float* __restrict__ A = which ? g_h : A_ext;
    const __nv_bfloat16* __restrict__ Whi = which ? g_W2hi : g_W1hi;
    const __nv_bfloat16* __restrict__ Wlo = which ? g_W2lo : g_W1lo;

    int tid = threadIdx.x;
    int wid = tid >> 5, lane = tid & 31;
    int g = lane >> 2, tg = lane & 3;
    int wm = (wid & 3) * 32, wn = (wid >> 2) * 64;
    int bm = blockIdx.x * 128;

    float acc[2][8][4];
#pragma unroll
    for (int i = 0; i < 2; i++)
#pragma unroll
        for (int j = 0; j < 8; j++)
#pragma unroll
            for (int q = 0; q < 4; q++) acc[i][j][q] = 0.f;

    int lr = tid >> 1;
    int lc = (tid & 1) * 16;
    bool arow_ok = (bm + lr) < M;
    const float4* ap = (const float4*)(A + (size_t)(bm + lr) * KK + lc);

    u32 smem_base;
    asm("{ .reg .u64 t; cvta.to.shared.u64 t, %1; cvt.u32.u64 %0, t; }"
        : "=r"(smem_base) : "l"((const void*)dsm));

    const __nv_bfloat16* srcBh = Whi + (size_t)(bn + lr) * 256 + lc;
    const __nv_bfloat16* srcBl = Wlo + (size_t)(bn + lr) * 256 + lc;

#define CPASYNC_B(kc, buf) do {                                                \
        u32 d0 = smem_base + 40960u + (u32)(buf) * 20480u                      \
                 + (u32)(lr * SSTR + lc) * 2u;                                 \
        cp16(d0,            srcBh + (kc));                                     \
        cp16(d0 + 16u,      srcBh + (kc) + 8);                                 \
        cp16(d0 + 10240u,   srcBl + (kc));                                     \
        cp16(d0 + 10240u + 16u, srcBl + (kc) + 8);                             \
        asm volatile("cp.async.commit_group;\n" ::: "memory");                 \
    } while (0)

    float4 pa[4];
#pragma unroll
    for (int j = 0; j < 4; j++)
        pa[j] = arow_ok ? ap[j] : make_float4(0.f, 0.f, 0.f, 0.f);
    CPASYNC_B(0, 0);
    STORE_A(pa, 0);
    asm volatile("cp.async.wait_group 0;\n" ::: "memory");
    __syncthreads();

    for (int c = 0; c < 8; c++) {
        int b = c & 1;
        if (c < 7) {
#pragma unroll
            for (int j = 0; j < 4; j++)
                pa[j] = arow_ok ? ap[8 * (c + 1) + j] : make_float4(0.f, 0.f, 0.f, 0.f);
            CPASYNC_B(32 * (c + 1), 1 - b);
        }
        {
            const __nv_bfloat16* cA = dsm + b * 10240;
            const __nv_bfloat16* cB = dsm + 20480 + b * 10240;
#pragma unroll
            for (int ks = 0; ks < 2; ks++) {
                int kb = ks * 16;
                u32 ahi[2][4], alo[2][4];
#pragma unroll
                for (int mi = 0; mi < 2; mi++) {
                    int r0 = wm + mi * 16 + g;
                    const __nv_bfloat16* ph = cA + r0 * SSTR + kb + tg * 2;
                    ahi[mi][0] = *(const u32*)ph;
                    ahi[mi][1] = *(const u32*)(ph + 8 * SSTR);
                    ahi[mi][2] = *(const u32*)(ph + 8);
                    ahi[mi][3] = *(const u32*)(ph + 8 * SSTR + 8);
                    const __nv_bfloat16* pl = ph + 5120;
                    alo[mi][0] = *(const u32*)pl;
                    alo[mi][1] = *(const u32*)(pl + 8 * SSTR);
                    alo[mi][2] = *(const u32*)(pl + 8);
                    alo[mi][3] = *(const u32*)(pl + 8 * SSTR + 8);
                }
#pragma unroll
                for (int ni = 0; ni < 8; ni++) {
                    int nr = wn + ni * 8 + g;
                    const __nv_bfloat16* pb = cB + nr * SSTR + kb + tg * 2;
                    u32 bh0 = *(const u32*)pb;
                    u32 bh1 = *(const u32*)(pb + 8);
                    u32 bl0 = *(const u32*)(pb + 5120);
                    u32 bl1 = *(const u32*)(pb + 5120 + 8);
#pragma unroll
                    for (int mi = 0; mi < 2; mi++) {
                        mma_bf16(acc[mi][ni], ahi[mi], bh0, bh1);
                        mma_bf16(acc[mi][ni], ahi[mi], bl0, bl1);
                        mma_bf16(acc[mi][ni], alo[mi], bh0, bh1);
                    }
                }
            }
        }
        if (c < 7) {
            STORE_A(pa, 1 - b);
            asm volatile("cp.async.wait_group 0;\n" ::: "memory");
            __syncthreads();
        }
    }

#pragma unroll
    for (int mi = 0; mi < 2; mi++) {
        int row0 = bm + wm + mi * 16 + g;
#pragma unroll
        for (int ni = 0; ni < 8; ni++) {
            int col = bn + wn + ni * 8 + tg * 2;
            if (row0 < M)
                *(float2*)&g_Y[(size_t)row0 * KK + col] =
                    make_float2(acc[mi][ni][0], acc[mi][ni][1]);
            if (row0 + 8 < M)
                *(float2*)&g_Y[(size_t)(row0 + 8) * KK + col] =
                    make_float2(acc[mi][ni][2], acc[mi][ni][3]);
        }
    }
#undef CPASYNC_B
}

// ---- layer 3: 128x64 tile, reads g_h2, writes g_Y[M][40] --------------------
__global__ void __launch_bounds__(256, 2) k_gemm_mma3(int M) {
    extern __shared__ __nv_bfloat16 dsm[];
    const float* __restrict__ A = g_h2;

    int tid = threadIdx.x;
    int wid = tid >> 5, lane = tid & 31;
    int g = lane >> 2, tg = lane & 3;
    int wm = (wid & 3) * 32, wn = (wid >> 2) * 32;
    int bm = blockIdx.x * 128;

    float acc[2][4][4];
#pragma unroll
    for (int i = 0; i < 2; i++)
#pragma unroll
        for (int j = 0; j < 4; j++)
#pragma unroll
            for (int q = 0; q < 4; q++) acc[i][j][q] = 0.f;

    int lr = tid >> 1;
    int lc = (tid & 1) * 16;
    bool arow_ok = (bm + lr) < M;
    const float4* ap = (const float4*)(A + (size_t)(bm + lr) * KK + lc);

    u32 smem_base;
    asm("{ .reg .u64 t; cvta.to.shared.u64 t, %1; cvt.u32.u64 %0, t; }"
        : "=r"(smem_base) : "l"((const void*)dsm));

    const __nv_bfloat16* srcBh = g_W3hi + (size_t)lr * 256 + lc;
    const __nv_bfloat16* srcBl = g_W3lo + (size_t)lr * 256 + lc;

#define CPASYNC_B3(kc, buf) do {                                               \
        if (lr < 64) {                                                         \
            u32 d0 = smem_base + 40960u + (u32)(buf) * 10240u                  \
                     + (u32)(lr * SSTR + lc) * 2u;                             \
            cp16(d0,           srcBh + (kc));                                  \
            cp16(d0 + 16u,     srcBh + (kc) + 8);                              \
            cp16(d0 + 5120u,   srcBl + (kc));                                  \
            cp16(d0 + 5120u + 16u, srcBl + (kc) + 8);                          \
        }                                                                      \
        asm volatile("cp.async.commit_group;\n" ::: "memory");                 \
    } while (0)

    float4 pa[4];
#pragma unroll
    for (int j = 0; j < 4; j++)
        pa[j] = arow_ok ? ap[j] : make_float4(0.f, 0.f, 0.f, 0.f);
    CPASYNC_B3(0, 0);
    STORE_A(pa, 0);
    asm volatile("cp.async.wait_group 0;\n" ::: "memory");
    __syncthreads();

    for (int c = 0; c < 8; c++) {
        int b = c & 1;
        if (c < 7) {
#pragma unroll
            for (int j = 0; j < 4; j++)
                pa[j] = arow_ok ? ap[8 * (c + 1) + j] : make_float4(0.f, 0.f, 0.f, 0.f);
            CPASYNC_B3(32 * (c + 1), 1 - b);
        }
        {
            const __nv_bfloat16* cA = dsm + b * 10240;
            const __nv_bfloat16* cB = dsm + 20480 + b * 5120;
#pragma unroll
            for (int ks = 0; ks < 2; ks++) {
                int kb = ks * 16;
                u32 ahi[2][4], alo[2][4];
#pragma unroll
                for (int mi = 0; mi < 2; mi++) {
                    int r0 = wm + mi * 16 + g;
                    const __nv_bfloat16* ph = cA + r0 * SSTR + kb + tg * 2;
                    ahi[mi][0] = *(const u32*)ph;
                    ahi[mi][1] = *(const u32*)(ph + 8 * SSTR);
                    ahi[mi][2] = *(const u32*)(ph + 8);
                    ahi[mi][3] = *(const u32*)(ph + 8 * SSTR + 8);
                    const __nv_bfloat16* pl = ph + 5120;
                    alo[mi][0] = *(const u32*)pl;
                    alo[mi][1] = *(const u32*)(pl + 8 * SSTR);
                    alo[mi][2] = *(const u32*)(pl + 8);
                    alo[mi][3] = *(const u32*)(pl + 8 * SSTR + 8);
                }
#pragma unroll
                for (int ni = 0; ni < 4; ni++) {
                    int nr = wn + ni * 8 + g;
                    const __nv_bfloat16* pb = cB + nr * SSTR + kb + tg * 2;
                    u32 bh0 = *(const u32*)pb;
                    u32 bh1 = *(const u32*)(pb + 8);
                    u32 bl0 = *(const u32*)(pb + 2560);
                    u32 bl1 = *(const u32*)(pb + 2560 + 8);
#pragma unroll
                    for (int mi = 0; mi < 2; mi++) {
                        mma_bf16(acc[mi][ni], ahi[mi], bh0, bh1);
                        mma_bf16(acc[mi][ni], ahi[mi], bl0, bl1);
                        mma_bf16(acc[mi][ni], alo[mi], bh0, bh1);
                    }
                }
            }
        }
        if (c < 7) {
            STORE_A(pa, 1 - b);
            asm volatile("cp.async.wait_group 0;\n" ::: "memory");
            __syncthreads();
        }
    }

#pragma unroll
    for (int mi = 0; mi < 2; mi++) {
        int row0 = bm + wm + mi * 16 + g;
#pragma unroll
        for (int ni = 0; ni < 4; ni++) {
            int col = wn + ni * 8 + tg * 2;
            if (col < CC) {
                if (row0 < M)
                    *(float2*)&g_Y[(size_t)row0 * CC + col] =
                        make_float2(acc[mi][ni][0], acc[mi][ni][1]);
                if (row0 + 8 < M)
                    *(float2*)&g_Y[(size_t)(row0 + 8) * CC + col] =
                        make_float2(acc[mi][ni][2], acc[mi][ni][3]);
            }
        }
    }
#undef CPASYNC_B3
}

// ---------------- CSR build --------------------------------------------------
__global__ void k_zero_counts(int n) {
    int i = blockIdx.x * blockDim.x + threadIdx.x;
    if (i < n) g_counts[i] = 0;
}
__global__ void k_hist(const int* __restrict__ edge, int E, int n) {
    int e = blockIdx.x * blockDim.x + threadIdx.x;
    if (e < E) {
        unsigned d = (unsigned)edge[E + e];
        if (d < (unsigned)n) atomicAdd(&g_counts[d], 1);
    }
}
__global__ void k_scan1(int n) {
    __shared__ int sh[1024];
    int i = blockIdx.x * 1024 + threadIdx.x;
    int v = (i < n) ? g_counts[i] : 0;
    sh[threadIdx.x] = v;
    __syncthreads();
    for (int off = 1; off < 1024; off <<= 1) {
        int t = (threadIdx.x >= off) ? sh[threadIdx.x - off] : 0;
        __syncthreads();
        sh[threadIdx.x] += t;
        __syncthreads();
    }
    if (i < n) g_indptr[i] = sh[threadIdx.x];
    if (threadIdx.x == 1023) g_blocksums[blockIdx.x] = sh[1023];
}
__global__ void k_scan2(int nb) {
    __shared__ int sh[64];
    int t = threadIdx.x;
    int v = (t < nb) ? g_blocksums[t] : 0;
    sh[t] = v;
    __syncthreads();
    for (int off = 1; off < 64; off <<= 1) {
        int x = (t >= off) ? sh[t - off] : 0;
        __syncthreads();
        sh[t] += x;
        __syncthreads();
    }
    g_blocksums[t] = sh[t] - v;
}
__global__ void k_scan3(int n, int Etot) {
    int i = blockIdx.x * 1024 + threadIdx.x;
    if (i < n) {
        int excl = g_indptr[i] - g_counts[i] + g_blocksums[blockIdx.x];
        g_indptr[i] = excl;
        g_cursor[i] = excl;
    }
    if (i == 0) g_indptr[n] = Etot;
}
__global__ void k_scatter(const int* __restrict__ edge, int E, int n) {
    int e = blockIdx.x * blockDim.x + threadIdx.x;
    if (e < E) {
        unsigned d = (unsigned)edge[E + e];
        unsigned s = (unsigned)edge[e];
        if (d < (unsigned)n && s < (unsigned)n) {
            int pos = atomicAdd(&g_cursor[d], 1);
            g_srcsorted[pos] = (int)s;
        }
    }
}

// ------ aggregation (128-col half) + bias + relu; outWhich: 0->g_h 1->g_h2 ---
__global__ void k_agg_relu(const float* __restrict__ bias, int colbase, int outWhich) {
    const float* __restrict__ Y = g_Y;
    float* __restrict__ outp = outWhich ? g_h2 : g_h;
    __shared__ int sidx[64];
    int node = blockIdx.x;
    int col = colbase + threadIdx.x;
    int start = g_indptr[node], end = g_indptr[node + 1];
    float acc = 0.f;
    for (int base = start; base < end; base += 64) {
        int m = end - base;
        if (m > 64) m = 64;
        if (threadIdx.x < m) sidx[threadIdx.x] = g_srcsorted[base + threadIdx.x];
        __syncthreads();
#pragma unroll 4
        for (int i = 0; i < m; i++) {
            acc += Y[(size_t)sidx[i] * KK + col];
        }
        __syncthreads();
    }
    outp[(size_t)node * KK + col] = fmaxf(acc + bias[col], 0.f);
}

// ---------------- aggregation (40-wide) + bias + log_softmax -----------------
__global__ void k_agg_lsm(const float* __restrict__ b3, float* __restrict__ out, int n) {
    const float* __restrict__ Y3 = g_Y;
    int warp = (blockIdx.x * blockDim.x + threadIdx.x) >> 5;
    int lane = threadIdx.x & 31;
    if (warp >= n) return;
    int start = g_indptr[warp], end = g_indptr[warp + 1];
    float acc0 = 0.f, acc1 = 0.f;
    for (int e = start; e < end; e++) {
        int s = g_srcsorted[e];
        acc0 += Y3[(size_t)s * CC + lane];
        if (lane < 8) acc1 += Y3[(size_t)s * CC + 32 + lane];
    }
    float v0 = acc0 + b3[lane];
    float v1 = (lane < 8) ? (acc1 + b3[32 + lane]) : -1e30f;
    float m = fmaxf(v0, v1);
#pragma unroll
    for (int off = 16; off; off >>= 1) m = fmaxf(m, __shfl_xor_sync(0xffffffffu, m, off));
    float s0 = expf(v0 - m) + ((lane < 8) ? expf(v1 - m) : 0.f);
#pragma unroll
    for (int off = 16; off; off >>= 1) s0 += __shfl_xor_sync(0xffffffffu, s0, off);
    float lse = m + logf(s0);
    out[(size_t)warp * CC + lane] = v0 - lse;
    if (lane < 8) out[(size_t)warp * CC + 32 + lane] = v1 - lse;
}

// ---------------- tail: node_count scalar(s) ---------------------------------
__global__ void k_tail(float* __restrict__ out, int begin, int total, float val) {
    int i = begin + blockIdx.x * blockDim.x + threadIdx.x;
    if (i < total) out[i] = val;
}

// ---------------- launch -----------------------------------------------------
extern "C" void kernel_launch(void* const* d_in, const int* in_sizes, int n_in,
                              void* d_out, int out_size) {
    const float* features = (const float*)d_in[0];
    const int*   edge     = (const int*)d_in[1];   // int32 (JAX x64 disabled)
    const float* W1 = (const float*)d_in[4];
    const float* b1 = (const float*)d_in[5];
    const float* W2 = (const float*)d_in[6];
    const float* b2 = (const float*)d_in[7];
    const float* W3 = (const float*)d_in[8];
    const float* b3 = (const float*)d_in[9];
    float* out = (float*)d_out;

    int n = in_sizes[0] / KK;      // 50000
    int E = in_sizes[1] / 2;       // 800000

    cudaFuncSetAttribute(k_gemm_mma, cudaFuncAttributeMaxDynamicSharedMemorySize,
                         SMEM_GEMM_BYTES);
    cudaFuncSetAttribute(k_gemm_mma3, cudaFuncAttributeMaxDynamicSharedMemorySize,
                         SMEM_GEMM3_BYTES);

    static cudaStream_t s2 = nullptr;
    static cudaEvent_t ev0 = nullptr, evG1a, evA1a, evG2a, evA2a, evCSR;
    if (!s2) {
        cudaStreamCreateWithFlags(&s2, cudaStreamNonBlocking);
        cudaEventCreateWithFlags(&ev0, cudaEventDisableTiming);
        cudaEventCreateWithFlags(&evG1a, cudaEventDisableTiming);
        cudaEventCreateWithFlags(&evA1a, cudaEventDisableTiming);
        cudaEventCreateWithFlags(&evG2a, cudaEventDisableTiming);
        cudaEventCreateWithFlags(&evA2a, cudaEventDisableTiming);
        cudaEventCreateWithFlags(&evCSR, cudaEventDisableTiming);
    }

    int gtc = (n + 127) / 128;     // 391

    // ---- fork ----
    cudaEventRecord(ev0, 0);
    cudaStreamWaitEvent(s2, ev0, 0);

    // s2: independent prep + CSR
    int nc_begin = n * CC;
    if (out_size > nc_begin) {
        int rem = out_size - nc_begin;
        k_tail<<<(rem + 255) / 256, 256, 0, s2>>>(out, nc_begin, out_size, 150000.0f);
    }
    k_prepW3<<<64, 256, 0, s2>>>(W3);
    k_zero_counts<<<(n + 255) / 256, 256, 0, s2>>>(n);
    k_hist<<<(E + 255) / 256, 256, 0, s2>>>(edge, E, n);
    int NB = (n + 1023) / 1024;
    k_scan1<<<NB, 1024, 0, s2>>>(n);
    k_scan2<<<1, 64, 0, s2>>>(NB);
    k_scan3<<<NB, 1024, 0, s2>>>(n, E);
    k_scatter<<<(E + 255) / 256, 256, 0, s2>>>(edge, E, n);
    cudaEventRecord(evCSR, s2);

    // main: weights + GEMM1 halves
    k_prepW<<<256, 256>>>(W1, W2);
    k_gemm_mma<<<gtc, 256, SMEM_GEMM_BYTES>>>(features, n, 0, 0);
    cudaEventRecord(evG1a, 0);
    k_gemm_mma<<<gtc, 256, SMEM_GEMM_BYTES>>>(features, n, 0, 128);

    // s2: agg1a (cols 0-127) overlapped with GEMM1b
    cudaStreamWaitEvent(s2, evG1a, 0);
    k_agg_relu<<<n, 128, 0, s2>>>(b1, 0, 0);
    cudaEventRecord(evA1a, s2);

    // main: agg1b (needs CSR + GEMM1b)
    cudaStreamWaitEvent(0, evCSR, 0);
    k_agg_relu<<<n, 128>>>(b1, 128, 0);

    // main: GEMM2 halves (need full g_h)
    cudaStreamWaitEvent(0, evA1a, 0);
    k_gemm_mma<<<gtc, 256, SMEM_GEMM_BYTES>>>(nullptr, n, 1, 0);
    cudaEventRecord(evG2a, 0);
    k_gemm_mma<<<gtc, 256, SMEM_GEMM_BYTES>>>(nullptr, n, 1, 128);

    // s2: agg2a -> g_h2 (cols 0-127), overlapped with GEMM2b
    cudaStreamWaitEvent(s2, evG2a, 0);
    k_agg_relu<<<n, 128, 0, s2>>>(b2, 0, 1);
    cudaEventRecord(evA2a, s2);

    // main: agg2b -> g_h2 (cols 128-255)
    k_agg_relu<<<n, 128>>>(b2, 128, 1);

    // main: layer 3 (needs full g_h2) + log_softmax
    cudaStreamWaitEvent(0, evA2a, 0);
    k_gemm_mma3<<<gtc, 256, SMEM_GEMM3_BYTES>>>(n);
    k_agg_lsm<<<(n * 32 + 255) / 256, 256>>>(b3, out, n);
}